// round 1
// baseline (speedup 1.0000x reference)
#include <cuda_runtime.h>
#include <math.h>

// Problem constants
#define NN   8192          // B*S nodes
#define DD   768           // hidden dim
#define EE   131072        // edges
#define HH   12            // heads
#define HDD  64            // head dim

// ---------------- scratch (static device globals; no allocation) ----------------
__device__ float g_q[NN * DD];
__device__ float g_k[NN * DD];
__device__ float g_v[NN * DD];
__device__ float g_h0[NN * DD];
__device__ float g_h1[NN * DD];
__device__ float g_y[NN * DD];
__device__ float g_score[EE * HH];     // scores, then attn in-place
__device__ int   g_cnt[NN];
__device__ int   g_rowptr[NN + 1];
__device__ int   g_cursor[NN];
__device__ int   g_csr_eid[EE];
__device__ int   g_csr_src[EE];
__device__ int   g_csr_dst[EE];

// ---------------- SGEMM: C = (A @ W^T + bias) * alpha (+ resid) ----------------
// A [M,768] row-major, W [768,768] row-major (both K-contiguous -> NT gemm)
__global__ __launch_bounds__(256, 2)
void sgemm_nt(const float* __restrict__ A, const float* __restrict__ W,
              const float* __restrict__ bias, const float* __restrict__ resid,
              float* __restrict__ C, float alpha)
{
    __shared__ float As[16][128];
    __shared__ float Bs[16][128];
    const int bm = blockIdx.y * 128;
    const int bn = blockIdx.x * 128;
    const int tid = threadIdx.x;
    const int tx = tid & 15;
    const int ty = tid >> 4;

    float acc[8][8];
#pragma unroll
    for (int i = 0; i < 8; i++)
#pragma unroll
        for (int j = 0; j < 8; j++) acc[i][j] = 0.f;

    for (int k0 = 0; k0 < DD; k0 += 16) {
#pragma unroll
        for (int l = 0; l < 2; l++) {
            int idx = tid + l * 256;
            int r = idx >> 2;
            int kq = (idx & 3) << 2;
            float4 a = *(const float4*)(A + (size_t)(bm + r) * DD + k0 + kq);
            float4 b = *(const float4*)(W + (size_t)(bn + r) * DD + k0 + kq);
            As[kq + 0][r] = a.x; As[kq + 1][r] = a.y; As[kq + 2][r] = a.z; As[kq + 3][r] = a.w;
            Bs[kq + 0][r] = b.x; Bs[kq + 1][r] = b.y; Bs[kq + 2][r] = b.z; Bs[kq + 3][r] = b.w;
        }
        __syncthreads();
#pragma unroll
        for (int k = 0; k < 16; k++) {
            float4 a0 = *(const float4*)&As[k][ty * 4];
            float4 a1 = *(const float4*)&As[k][64 + ty * 4];
            float4 b0 = *(const float4*)&Bs[k][tx * 4];
            float4 b1 = *(const float4*)&Bs[k][64 + tx * 4];
            float av[8] = {a0.x, a0.y, a0.z, a0.w, a1.x, a1.y, a1.z, a1.w};
            float bv[8] = {b0.x, b0.y, b0.z, b0.w, b1.x, b1.y, b1.z, b1.w};
#pragma unroll
            for (int i = 0; i < 8; i++)
#pragma unroll
                for (int j = 0; j < 8; j++) acc[i][j] = fmaf(av[i], bv[j], acc[i][j]);
        }
        __syncthreads();
    }

#pragma unroll
    for (int i = 0; i < 8; i++) {
        int row = bm + ((i < 4) ? (ty * 4 + i) : (64 + ty * 4 + i - 4));
#pragma unroll
        for (int j = 0; j < 8; j++) {
            int col = bn + ((j < 4) ? (tx * 4 + j) : (64 + tx * 4 + j - 4));
            float v = (acc[i][j] + bias[col]) * alpha;
            if (resid) v += resid[(size_t)row * DD + col];
            C[(size_t)row * DD + col] = v;
        }
    }
}

// ---------------- CSR build ----------------
__global__ void hist_kernel(const int* __restrict__ dst)
{
    int e = blockIdx.x * blockDim.x + threadIdx.x;
    if (e < EE) atomicAdd(&g_cnt[dst[e]], 1);
}

__global__ void scan_kernel()
{
    __shared__ int sh[1024];
    int t = threadIdx.x;
    int base = t * 8;
    int loc[8];
    int s = 0;
#pragma unroll
    for (int j = 0; j < 8; j++) { loc[j] = s; s += g_cnt[base + j]; }
    sh[t] = s;
    __syncthreads();
    for (int off = 1; off < 1024; off <<= 1) {
        int v = (t >= off) ? sh[t - off] : 0;
        __syncthreads();
        sh[t] += v;
        __syncthreads();
    }
    int excl = (t > 0) ? sh[t - 1] : 0;
#pragma unroll
    for (int j = 0; j < 8; j++) {
        g_rowptr[base + j] = excl + loc[j];
        g_cursor[base + j] = excl + loc[j];
    }
    if (t == 1023) g_rowptr[NN] = excl + s;
}

__global__ void scatter_kernel(const int* __restrict__ dst)
{
    int e = blockIdx.x * blockDim.x + threadIdx.x;
    if (e < EE) {
        int p = atomicAdd(&g_cursor[dst[e]], 1);
        g_csr_eid[p] = e;
    }
}

// per-row sort by original edge id -> deterministic fp reduction order
__global__ void sort_rows_kernel(const int* __restrict__ edge_src)
{
    int n = blockIdx.x;
    int r0 = g_rowptr[n], r1 = g_rowptr[n + 1];
    int deg = r1 - r0;
    int lane = threadIdx.x;
    __shared__ int sh[2048];
    if (deg <= 2048) {
        for (int i = lane; i < deg; i += 32) sh[i] = g_csr_eid[r0 + i];
        __syncwarp();
        for (int p = 0; p < deg; p++) {
            for (int i = (p & 1) + 2 * lane; i + 1 < deg; i += 64) {
                int a = sh[i], b = sh[i + 1];
                if (a > b) { sh[i] = b; sh[i + 1] = a; }
            }
            __syncwarp();
        }
        for (int i = lane; i < deg; i += 32) {
            int e = sh[i];
            g_csr_eid[r0 + i] = e;
            g_csr_src[r0 + i] = edge_src[e];
            g_csr_dst[r0 + i] = n;
        }
    } else {  // pathological fallback (never hit for this input)
        for (int i = lane; i < deg; i += 32) {
            int e = g_csr_eid[r0 + i];
            g_csr_src[r0 + i] = edge_src[e];
            g_csr_dst[r0 + i] = n;
        }
    }
}

// ---------------- edge scores: score[i,h] = k[src]·q[dst] per head ----------------
__global__ void score_kernel(const float* __restrict__ mask)
{
    int gw = (blockIdx.x * blockDim.x + threadIdx.x) >> 5;
    int lane = threadIdx.x & 31;
    if (gw >= EE) return;
    int src = g_csr_src[gw];
    int dst = g_csr_dst[gw];
    const float* kk = g_k + (size_t)src * DD;
    const float* qq = g_q + (size_t)dst * DD;
    bool m = (mask[dst] >= 0.f);
#pragma unroll
    for (int h = 0; h < HH; h++) {
        int o = h * HDD + lane;
        float p = kk[o] * qq[o] + kk[o + 32] * qq[o + 32];
#pragma unroll
        for (int off = 16; off > 0; off >>= 1)
            p += __shfl_xor_sync(0xffffffffu, p, off);
        if (lane == 0) g_score[(size_t)gw * HH + h] = m ? p : -1e4f;
    }
}

// ---------------- per-dst softmax over incoming edges (warp/node, lane=head) ----
__global__ void softmax_kernel()
{
    int node = blockIdx.x * 4 + (threadIdx.x >> 5);
    int lane = threadIdx.x & 31;
    if (node >= NN || lane >= HH) return;
    int r0 = g_rowptr[node], r1 = g_rowptr[node + 1];
    float mx = -3.4e38f;
    for (int i = r0; i < r1; i++) mx = fmaxf(mx, g_score[(size_t)i * HH + lane]);
    float s = 0.f;
    for (int i = r0; i < r1; i++) s += expf(g_score[(size_t)i * HH + lane] - mx);
    float inv = 1.f / s;
    for (int i = r0; i < r1; i++) {
        float a = expf(g_score[(size_t)i * HH + lane] - mx) * inv;
        g_score[(size_t)i * HH + lane] = a;
    }
}

// ---------------- message passing: h_out = 0.9 * sum_e attn*h_in[src] + 0.1*v ----
__global__ void mp_kernel(const float* __restrict__ hin, float* __restrict__ hout)
{
    int n = blockIdx.x;
    int t = threadIdx.x;   // 256 threads; each owns dims t, t+256, t+512
    int r0 = g_rowptr[n], r1 = g_rowptr[n + 1];
    int hh = t >> 6;
    float a0 = 0.f, a1 = 0.f, a2 = 0.f;
    for (int i = r0; i < r1; i++) {
        const float* hs = hin + (size_t)g_csr_src[i] * DD;
        const float* at = g_score + (size_t)i * HH;
        a0 = fmaf(at[hh],     hs[t],        a0);
        a1 = fmaf(at[hh + 4], hs[t + 256],  a1);
        a2 = fmaf(at[hh + 8], hs[t + 512],  a2);
    }
    const float* vv = g_v + (size_t)n * DD;
    float* o = hout + (size_t)n * DD;
    o[t]       = 0.9f * a0 + 0.1f * vv[t];
    o[t + 256] = 0.9f * a1 + 0.1f * vv[t + 256];
    o[t + 512] = 0.9f * a2 + 0.1f * vv[t + 512];
}

// ---------------- residual layernorm ----------------
__global__ void layernorm_kernel(const float* __restrict__ y,
                                 const float* __restrict__ gam,
                                 const float* __restrict__ bet,
                                 float* __restrict__ out)
{
    int row = blockIdx.x;
    int t = threadIdx.x;  // 256
    const float* yr = y + (size_t)row * DD;
    float v0 = yr[t], v1 = yr[t + 256], v2 = yr[t + 512];
    __shared__ float sh[256];
    sh[t] = v0 + v1 + v2;
    __syncthreads();
    for (int o = 128; o > 0; o >>= 1) { if (t < o) sh[t] += sh[t + o]; __syncthreads(); }
    float mu = sh[0] * (1.f / 768.f);
    __syncthreads();
    float d0 = v0 - mu, d1 = v1 - mu, d2 = v2 - mu;
    sh[t] = d0 * d0 + d1 * d1 + d2 * d2;
    __syncthreads();
    for (int o = 128; o > 0; o >>= 1) { if (t < o) sh[t] += sh[t + o]; __syncthreads(); }
    float inv = rsqrtf(sh[0] * (1.f / 768.f) + 1e-12f);
    float* orow = out + (size_t)row * DD;
    orow[t]       = d0 * inv * gam[t]       + bet[t];
    orow[t + 256] = d1 * inv * gam[t + 256] + bet[t + 256];
    orow[t + 512] = d2 * inv * gam[t + 512] + bet[t + 512];
}

// ---------------- launch ----------------
extern "C" void kernel_launch(void* const* d_in, const int* in_sizes, int n_in,
                              void* d_out, int out_size)
{
    const float* x    = (const float*)d_in[0];   // hidden_states [2,4096,768]
    const float* mask = (const float*)d_in[1];   // attention_mask [2,4096]
    const int*   esrc = (const int*)d_in[2];
    const int*   edst = (const int*)d_in[3];
    const float* Wq = (const float*)d_in[4];  const float* bq = (const float*)d_in[5];
    const float* Wk = (const float*)d_in[6];  const float* bk = (const float*)d_in[7];
    const float* Wv = (const float*)d_in[8];  const float* bv = (const float*)d_in[9];
    const float* Wo = (const float*)d_in[10]; const float* bo = (const float*)d_in[11];
    const float* lg = (const float*)d_in[12]; const float* lb = (const float*)d_in[13];
    float* out = (float*)d_out;

    float *qp, *kp, *vp, *h0p, *h1p, *yp;
    int* cntp;
    cudaGetSymbolAddress((void**)&qp,  g_q);
    cudaGetSymbolAddress((void**)&kp,  g_k);
    cudaGetSymbolAddress((void**)&vp,  g_v);
    cudaGetSymbolAddress((void**)&h0p, g_h0);
    cudaGetSymbolAddress((void**)&h1p, g_h1);
    cudaGetSymbolAddress((void**)&yp,  g_y);
    cudaGetSymbolAddress((void**)&cntp, g_cnt);

    dim3 ggrid(DD / 128, NN / 128);   // (6, 64)

    // q,k,v projections (q pre-scaled by 1/sqrt(HD)=0.125, applied to bias too)
    sgemm_nt<<<ggrid, 256>>>(x, Wq, bq, nullptr, qp, 0.125f);
    sgemm_nt<<<ggrid, 256>>>(x, Wk, bk, nullptr, kp, 1.0f);
    sgemm_nt<<<ggrid, 256>>>(x, Wv, bv, nullptr, vp, 1.0f);

    // CSR build (deterministic: per-row sort by edge id)
    cudaMemsetAsync(cntp, 0, NN * sizeof(int), 0);
    hist_kernel<<<(EE + 255) / 256, 256>>>(edst);
    scan_kernel<<<1, 1024>>>();
    scatter_kernel<<<(EE + 255) / 256, 256>>>(edst);
    sort_rows_kernel<<<NN, 32>>>(esrc);

    // edge scores + per-dst softmax
    score_kernel<<<EE * 32 / 256, 256>>>(mask);
    softmax_kernel<<<NN / 4, 128>>>();

    // 5 message-passing steps (ping-pong: v -> h0 -> h1 -> h0 -> h1 -> h0)
    mp_kernel<<<NN, 256>>>(vp,  h0p);
    mp_kernel<<<NN, 256>>>(h0p, h1p);
    mp_kernel<<<NN, 256>>>(h1p, h0p);
    mp_kernel<<<NN, 256>>>(h0p, h1p);
    mp_kernel<<<NN, 256>>>(h1p, h0p);

    // output projection + residual, then layernorm
    sgemm_nt<<<ggrid, 256>>>(h0p, Wo, bo, x, yp, 1.0f);
    layernorm_kernel<<<NN, 256>>>(yp, lg, lb, out);
}

// round 4
// speedup vs baseline: 1.8703x; 1.8703x over previous
#include <cuda_runtime.h>
#include <cstdint>
#include <math.h>

// Problem constants
#define NN   8192          // B*S nodes
#define DD   768           // hidden dim
#define EE   131072        // edges
#define HH   12            // heads
#define HDD  64            // head dim

// ---------------- scratch (static device globals; no allocation) ----------------
__device__ float g_q[NN * DD];
__device__ float g_k[NN * DD];
__device__ float g_v[NN * DD];
__device__ float g_h0[NN * DD];
__device__ float g_h1[NN * DD];
__device__ float g_y[NN * DD];
__device__ float g_score[EE * HH];     // scores, then attn in-place
__device__ int   g_cnt[NN];
__device__ int   g_rowptr[NN + 1];
__device__ int   g_cursor[NN];
__device__ int   g_csr_eid[EE];
__device__ int   g_csr_src[EE];
__device__ int   g_csr_dst[EE];

// ================= tf32 warp-MMA GEMM: C = (A @ W^T + bias)*alpha (+resid) =====
// A [M,768] row-major, W [768,768] row-major (both K-contiguous -> NT GEMM).
// mma.sync.m16n8k8 tf32 path (works on plain sm_100 target).

__device__ __forceinline__ uint32_t f2tf32(float x) {
    uint32_t r;
    asm("cvt.rna.tf32.f32 %0, %1;" : "=r"(r) : "f"(x));
    return r;
}

__device__ __forceinline__ uint32_t smem_cast(const void* p) {
    return (uint32_t)__cvta_generic_to_shared(p);
}

#define BKK     32
#define LDA     36                      // 32 + 4 pad floats per row
#define STG_FL  (128 * LDA * 2)         // floats per stage (A + B tiles)
#define GEMM_SMEM (2 * STG_FL * 4)      // 2 stages, bytes = 73728

__global__ __launch_bounds__(256, 2)
void gemm_tf32(const float* __restrict__ A, const float* __restrict__ W,
               const float* __restrict__ bias, const float* __restrict__ resid,
               float* __restrict__ C, float alpha)
{
    extern __shared__ float sm[];
    const int tid  = threadIdx.x;
    const int wid  = tid >> 5;
    const int lane = tid & 31;
    const int g    = lane >> 2;        // group id 0..7
    const int tg   = lane & 3;         // thread-in-group 0..3
    const int wm   = wid >> 2;         // 0..1  (M dir, 64 rows each)
    const int wn   = wid & 3;          // 0..3  (N dir, 32 cols each)
    const int bm   = blockIdx.y * 128;
    const int bn   = blockIdx.x * 128;

    const float* Ab = A + (size_t)bm * DD;
    const float* Wb = W + (size_t)bn * DD;

    float acc[4][4][4];
#pragma unroll
    for (int mt = 0; mt < 4; mt++)
#pragma unroll
        for (int nt = 0; nt < 4; nt++)
#pragma unroll
            for (int c = 0; c < 4; c++) acc[mt][nt][c] = 0.f;

    // ---- async stage loader: 128x32 floats for A and for B per stage ----
    auto load_stage = [&](int kt, int stg) {
        float* Abase = sm + stg * STG_FL;
        float* Bbase = Abase + 128 * LDA;
#pragma unroll
        for (int i = 0; i < 4; i++) {
            int idx = tid + i * 256;           // 0..1023 float4 slots
            int row = idx >> 3;
            int c4  = idx & 7;
            const float* ga = Ab + (size_t)row * DD + kt * BKK + c4 * 4;
            const float* gb = Wb + (size_t)row * DD + kt * BKK + c4 * 4;
            uint32_t da = smem_cast(Abase + row * LDA + c4 * 4);
            uint32_t db = smem_cast(Bbase + row * LDA + c4 * 4);
            asm volatile("cp.async.cg.shared.global [%0], [%1], 16;" :: "r"(da), "l"(ga));
            asm volatile("cp.async.cg.shared.global [%0], [%1], 16;" :: "r"(db), "l"(gb));
        }
        asm volatile("cp.async.commit_group;");
    };

    load_stage(0, 0);   // prologue

    const int NKT = DD / BKK;   // 24
    for (int kt = 0; kt < NKT; kt++) {
        asm volatile("cp.async.wait_group 0;");
        __syncthreads();
        if (kt + 1 < NKT) load_stage(kt + 1, (kt + 1) & 1);

        const float* Abase = sm + (kt & 1) * STG_FL;
        const float* Bbase = Abase + 128 * LDA;
        const float* Aw = Abase + (wm * 64) * LDA;
        const float* Bw = Bbase + (wn * 32) * LDA;

#pragma unroll
        for (int ks = 0; ks < 4; ks++) {
            const int k0 = ks * 8;
            uint32_t bf[4][2];
#pragma unroll
            for (int nt = 0; nt < 4; nt++) {
                const float* bp = Bw + (nt * 8 + g) * LDA + k0;
                bf[nt][0] = f2tf32(bp[tg]);
                bf[nt][1] = f2tf32(bp[tg + 4]);
            }
#pragma unroll
            for (int mt = 0; mt < 4; mt++) {
                const float* ap0 = Aw + (mt * 16 + g) * LDA + k0;
                const float* ap1 = ap0 + 8 * LDA;
                uint32_t a0 = f2tf32(ap0[tg]);
                uint32_t a1 = f2tf32(ap1[tg]);
                uint32_t a2 = f2tf32(ap0[tg + 4]);
                uint32_t a3 = f2tf32(ap1[tg + 4]);
#pragma unroll
                for (int nt = 0; nt < 4; nt++) {
                    asm volatile(
                        "mma.sync.aligned.m16n8k8.row.col.f32.tf32.tf32.f32 "
                        "{%0,%1,%2,%3}, {%4,%5,%6,%7}, {%8,%9}, {%0,%1,%2,%3};"
                        : "+f"(acc[mt][nt][0]), "+f"(acc[mt][nt][1]),
                          "+f"(acc[mt][nt][2]), "+f"(acc[mt][nt][3])
                        : "r"(a0), "r"(a1), "r"(a2), "r"(a3),
                          "r"(bf[nt][0]), "r"(bf[nt][1]));
                }
            }
        }
    }

    // ---- epilogue ----
#pragma unroll
    for (int mt = 0; mt < 4; mt++) {
        int r0 = bm + wm * 64 + mt * 16 + g;
        int r1 = r0 + 8;
#pragma unroll
        for (int nt = 0; nt < 4; nt++) {
            int col = bn + wn * 32 + nt * 8 + tg * 2;
            float b0 = bias[col], b1 = bias[col + 1];
            float2 o0, o1;
            o0.x = (acc[mt][nt][0] + b0) * alpha;
            o0.y = (acc[mt][nt][1] + b1) * alpha;
            o1.x = (acc[mt][nt][2] + b0) * alpha;
            o1.y = (acc[mt][nt][3] + b1) * alpha;
            if (resid) {
                o0.x += resid[(size_t)r0 * DD + col];
                o0.y += resid[(size_t)r0 * DD + col + 1];
                o1.x += resid[(size_t)r1 * DD + col];
                o1.y += resid[(size_t)r1 * DD + col + 1];
            }
            *(float2*)(C + (size_t)r0 * DD + col) = o0;
            *(float2*)(C + (size_t)r1 * DD + col) = o1;
        }
    }
}

// ---------------- CSR build ----------------
__global__ void hist_kernel(const int* __restrict__ dst)
{
    int e = blockIdx.x * blockDim.x + threadIdx.x;
    if (e < EE) atomicAdd(&g_cnt[dst[e]], 1);
}

__global__ void scan_kernel()
{
    __shared__ int sh[1024];
    int t = threadIdx.x;
    int base = t * 8;
    int loc[8];
    int s = 0;
#pragma unroll
    for (int j = 0; j < 8; j++) { loc[j] = s; s += g_cnt[base + j]; }
    sh[t] = s;
    __syncthreads();
    for (int off = 1; off < 1024; off <<= 1) {
        int v = (t >= off) ? sh[t - off] : 0;
        __syncthreads();
        sh[t] += v;
        __syncthreads();
    }
    int excl = (t > 0) ? sh[t - 1] : 0;
#pragma unroll
    for (int j = 0; j < 8; j++) {
        g_rowptr[base + j] = excl + loc[j];
        g_cursor[base + j] = excl + loc[j];
    }
    if (t == 1023) g_rowptr[NN] = excl + s;
}

__global__ void scatter_kernel(const int* __restrict__ dst)
{
    int e = blockIdx.x * blockDim.x + threadIdx.x;
    if (e < EE) {
        int p = atomicAdd(&g_cursor[dst[e]], 1);
        g_csr_eid[p] = e;
    }
}

// per-row sort by original edge id -> deterministic fp reduction order
__global__ void sort_rows_kernel(const int* __restrict__ edge_src)
{
    int n = blockIdx.x;
    int r0 = g_rowptr[n], r1 = g_rowptr[n + 1];
    int deg = r1 - r0;
    int lane = threadIdx.x;
    __shared__ int sh[2048];
    if (deg <= 2048) {
        for (int i = lane; i < deg; i += 32) sh[i] = g_csr_eid[r0 + i];
        __syncwarp();
        for (int p = 0; p < deg; p++) {
            for (int i = (p & 1) + 2 * lane; i + 1 < deg; i += 64) {
                int a = sh[i], b = sh[i + 1];
                if (a > b) { sh[i] = b; sh[i + 1] = a; }
            }
            __syncwarp();
        }
        for (int i = lane; i < deg; i += 32) {
            int e = sh[i];
            g_csr_eid[r0 + i] = e;
            g_csr_src[r0 + i] = edge_src[e];
            g_csr_dst[r0 + i] = n;
        }
    } else {
        for (int i = lane; i < deg; i += 32) {
            int e = g_csr_eid[r0 + i];
            g_csr_src[r0 + i] = edge_src[e];
            g_csr_dst[r0 + i] = n;
        }
    }
}

// ---------------- edge scores: score[i,h] = k[src]·q[dst] per head ----------------
__global__ void score_kernel(const float* __restrict__ mask)
{
    int gw = (blockIdx.x * blockDim.x + threadIdx.x) >> 5;
    int lane = threadIdx.x & 31;
    if (gw >= EE) return;
    int src = g_csr_src[gw];
    int dst = g_csr_dst[gw];
    const float* kk = g_k + (size_t)src * DD;
    const float* qq = g_q + (size_t)dst * DD;
    bool m = (mask[dst] >= 0.f);
#pragma unroll
    for (int h = 0; h < HH; h++) {
        int o = h * HDD + lane;
        float p = kk[o] * qq[o] + kk[o + 32] * qq[o + 32];
#pragma unroll
        for (int off = 16; off > 0; off >>= 1)
            p += __shfl_xor_sync(0xffffffffu, p, off);
        if (lane == 0) g_score[(size_t)gw * HH + h] = m ? p : -1e4f;
    }
}

// ---------------- per-dst softmax over incoming edges (warp/node, lane=head) ----
__global__ void softmax_kernel()
{
    int node = blockIdx.x * 4 + (threadIdx.x >> 5);
    int lane = threadIdx.x & 31;
    if (node >= NN || lane >= HH) return;
    int r0 = g_rowptr[node], r1 = g_rowptr[node + 1];
    float mx = -3.4e38f;
    for (int i = r0; i < r1; i++) mx = fmaxf(mx, g_score[(size_t)i * HH + lane]);
    float s = 0.f;
    for (int i = r0; i < r1; i++) s += expf(g_score[(size_t)i * HH + lane] - mx);
    float inv = 1.f / s;
    for (int i = r0; i < r1; i++) {
        float a = expf(g_score[(size_t)i * HH + lane] - mx) * inv;
        g_score[(size_t)i * HH + lane] = a;
    }
}

// ---------------- message passing: h_out = 0.9 * sum_e attn*h_in[src] + 0.1*v ----
__global__ void mp_kernel(const float* __restrict__ hin, float* __restrict__ hout)
{
    int n = blockIdx.x;
    int t = threadIdx.x;   // 256 threads; each owns dims t, t+256, t+512
    int r0 = g_rowptr[n], r1 = g_rowptr[n + 1];
    int hh = t >> 6;
    float a0 = 0.f, a1 = 0.f, a2 = 0.f;
    for (int i = r0; i < r1; i++) {
        const float* hs = hin + (size_t)g_csr_src[i] * DD;
        const float* at = g_score + (size_t)i * HH;
        a0 = fmaf(at[hh],     hs[t],        a0);
        a1 = fmaf(at[hh + 4], hs[t + 256],  a1);
        a2 = fmaf(at[hh + 8], hs[t + 512],  a2);
    }
    const float* vv = g_v + (size_t)n * DD;
    float* o = hout + (size_t)n * DD;
    o[t]       = 0.9f * a0 + 0.1f * vv[t];
    o[t + 256] = 0.9f * a1 + 0.1f * vv[t + 256];
    o[t + 512] = 0.9f * a2 + 0.1f * vv[t + 512];
}

// ---------------- residual layernorm ----------------
__global__ void layernorm_kernel(const float* __restrict__ y,
                                 const float* __restrict__ gam,
                                 const float* __restrict__ bet,
                                 float* __restrict__ out)
{
    int row = blockIdx.x;
    int t = threadIdx.x;  // 256
    const float* yr = y + (size_t)row * DD;
    float v0 = yr[t], v1 = yr[t + 256], v2 = yr[t + 512];
    __shared__ float sh[256];
    sh[t] = v0 + v1 + v2;
    __syncthreads();
    for (int o = 128; o > 0; o >>= 1) { if (t < o) sh[t] += sh[t + o]; __syncthreads(); }
    float mu = sh[0] * (1.f / 768.f);
    __syncthreads();
    float d0 = v0 - mu, d1 = v1 - mu, d2 = v2 - mu;
    sh[t] = d0 * d0 + d1 * d1 + d2 * d2;
    __syncthreads();
    for (int o = 128; o > 0; o >>= 1) { if (t < o) sh[t] += sh[t + o]; __syncthreads(); }
    float inv = rsqrtf(sh[0] * (1.f / 768.f) + 1e-12f);
    float* orow = out + (size_t)row * DD;
    orow[t]       = d0 * inv * gam[t]       + bet[t];
    orow[t + 256] = d1 * inv * gam[t + 256] + bet[t + 256];
    orow[t + 512] = d2 * inv * gam[t + 512] + bet[t + 512];
}

// ---------------- launch ----------------
extern "C" void kernel_launch(void* const* d_in, const int* in_sizes, int n_in,
                              void* d_out, int out_size)
{
    const float* x    = (const float*)d_in[0];   // hidden_states [2,4096,768]
    const float* mask = (const float*)d_in[1];   // attention_mask [2,4096]
    const int*   esrc = (const int*)d_in[2];
    const int*   edst = (const int*)d_in[3];
    const float* Wq = (const float*)d_in[4];  const float* bq = (const float*)d_in[5];
    const float* Wk = (const float*)d_in[6];  const float* bk = (const float*)d_in[7];
    const float* Wv = (const float*)d_in[8];  const float* bv = (const float*)d_in[9];
    const float* Wo = (const float*)d_in[10]; const float* bo = (const float*)d_in[11];
    const float* lg = (const float*)d_in[12]; const float* lb = (const float*)d_in[13];
    float* out = (float*)d_out;

    float *qp, *kp, *vp, *h0p, *h1p, *yp;
    int* cntp;
    cudaGetSymbolAddress((void**)&qp,  g_q);
    cudaGetSymbolAddress((void**)&kp,  g_k);
    cudaGetSymbolAddress((void**)&vp,  g_v);
    cudaGetSymbolAddress((void**)&h0p, g_h0);
    cudaGetSymbolAddress((void**)&h1p, g_h1);
    cudaGetSymbolAddress((void**)&yp,  g_y);
    cudaGetSymbolAddress((void**)&cntp, g_cnt);

    cudaFuncSetAttribute(gemm_tf32, cudaFuncAttributeMaxDynamicSharedMemorySize, GEMM_SMEM);

    dim3 ggrid(DD / 128, NN / 128);   // (6, 64)

    // q,k,v projections (q pre-scaled by 1/sqrt(HD)=0.125, applied to bias too)
    gemm_tf32<<<ggrid, 256, GEMM_SMEM>>>(x, Wq, bq, nullptr, qp, 0.125f);
    gemm_tf32<<<ggrid, 256, GEMM_SMEM>>>(x, Wk, bk, nullptr, kp, 1.0f);
    gemm_tf32<<<ggrid, 256, GEMM_SMEM>>>(x, Wv, bv, nullptr, vp, 1.0f);

    // CSR build (deterministic: per-row sort by edge id)
    cudaMemsetAsync(cntp, 0, NN * sizeof(int), 0);
    hist_kernel<<<(EE + 255) / 256, 256>>>(edst);
    scan_kernel<<<1, 1024>>>();
    scatter_kernel<<<(EE + 255) / 256, 256>>>(edst);
    sort_rows_kernel<<<NN, 32>>>(esrc);

    // edge scores + per-dst softmax
    score_kernel<<<EE * 32 / 256, 256>>>(mask);
    softmax_kernel<<<NN / 4, 128>>>();

    // 5 message-passing steps (ping-pong: v -> h0 -> h1 -> h0 -> h1 -> h0)
    mp_kernel<<<NN, 256>>>(vp,  h0p);
    mp_kernel<<<NN, 256>>>(h0p, h1p);
    mp_kernel<<<NN, 256>>>(h1p, h0p);
    mp_kernel<<<NN, 256>>>(h0p, h1p);
    mp_kernel<<<NN, 256>>>(h1p, h0p);

    // output projection + residual, then layernorm
    gemm_tf32<<<ggrid, 256, GEMM_SMEM>>>(h0p, Wo, bo, x, yp, 1.0f);
    layernorm_kernel<<<NN, 256>>>(yp, lg, lb, out);
}

// round 5
// speedup vs baseline: 2.1925x; 1.1723x over previous
#include <cuda_runtime.h>
#include <cuda_bf16.h>
#include <cstdint>
#include <math.h>

// Problem constants
#define NN   8192          // B*S nodes
#define DD   768           // hidden dim
#define EE   131072        // edges
#define HH   12            // heads
#define HDD  64            // head dim

// ---------------- scratch (static device globals; no allocation) ----------------
__device__ float g_v[NN * DD];
__device__ float g_hf[NN * DD];            // final h (fp32) for Wo GEMM
__device__ float g_y[NN * DD];
__device__ __nv_bfloat16 g_qh[NN * DD];    // q (bf16, pre-scaled)
__device__ __nv_bfloat16 g_kh[NN * DD];    // k (bf16)
__device__ __nv_bfloat16 g_vh[NN * DD];    // v (bf16, mp step-1 gather input)
__device__ __nv_bfloat16 g_hb0[NN * DD];   // h ping (bf16)
__device__ __nv_bfloat16 g_hb1[NN * DD];   // h pong (bf16)
__device__ float g_score[EE * HH];         // scores, then attn in-place
__device__ int   g_cnt[NN];
__device__ int   g_rowptr[NN + 1];
__device__ int   g_cursor[NN];
__device__ int   g_csr_eid[EE];
__device__ int   g_csr_src[EE];
__device__ int   g_csr_dst[EE];

// ================= tf32 warp-MMA GEMM =====
// C = (A @ W^T + bias)*alpha (+resid); optional fp32 C and/or bf16 Cb outputs.
// A [M,768] row-major, W [768,768] row-major (both K-contiguous -> NT GEMM).

__device__ __forceinline__ uint32_t f2tf32(float x) {
    uint32_t r;
    asm("cvt.rna.tf32.f32 %0, %1;" : "=r"(r) : "f"(x));
    return r;
}

__device__ __forceinline__ uint32_t smem_cast(const void* p) {
    return (uint32_t)__cvta_generic_to_shared(p);
}

#define BKK     32
#define LDA     36                      // 32 + 4 pad floats per row
#define STG_FL  (128 * LDA * 2)         // floats per stage (A + B tiles)
#define GEMM_SMEM (2 * STG_FL * 4)      // 2 stages, bytes = 73728

__global__ __launch_bounds__(256, 2)
void gemm_tf32(const float* __restrict__ A, const float* __restrict__ W,
               const float* __restrict__ bias, const float* __restrict__ resid,
               float* __restrict__ C, __nv_bfloat16* __restrict__ Cb, float alpha)
{
    extern __shared__ float sm[];
    const int tid  = threadIdx.x;
    const int wid  = tid >> 5;
    const int lane = tid & 31;
    const int g    = lane >> 2;        // group id 0..7
    const int tg   = lane & 3;         // thread-in-group 0..3
    const int wm   = wid >> 2;         // 0..1  (M dir, 64 rows each)
    const int wn   = wid & 3;          // 0..3  (N dir, 32 cols each)
    const int bm   = blockIdx.y * 128;
    const int bn   = blockIdx.x * 128;

    const float* Ab = A + (size_t)bm * DD;
    const float* Wb = W + (size_t)bn * DD;

    float acc[4][4][4];
#pragma unroll
    for (int mt = 0; mt < 4; mt++)
#pragma unroll
        for (int nt = 0; nt < 4; nt++)
#pragma unroll
            for (int c = 0; c < 4; c++) acc[mt][nt][c] = 0.f;

    auto load_stage = [&](int kt, int stg) {
        float* Abase = sm + stg * STG_FL;
        float* Bbase = Abase + 128 * LDA;
#pragma unroll
        for (int i = 0; i < 4; i++) {
            int idx = tid + i * 256;           // 0..1023 float4 slots
            int row = idx >> 3;
            int c4  = idx & 7;
            const float* ga = Ab + (size_t)row * DD + kt * BKK + c4 * 4;
            const float* gb = Wb + (size_t)row * DD + kt * BKK + c4 * 4;
            uint32_t da = smem_cast(Abase + row * LDA + c4 * 4);
            uint32_t db = smem_cast(Bbase + row * LDA + c4 * 4);
            asm volatile("cp.async.cg.shared.global [%0], [%1], 16;" :: "r"(da), "l"(ga));
            asm volatile("cp.async.cg.shared.global [%0], [%1], 16;" :: "r"(db), "l"(gb));
        }
        asm volatile("cp.async.commit_group;");
    };

    load_stage(0, 0);   // prologue

    const int NKT = DD / BKK;   // 24
    for (int kt = 0; kt < NKT; kt++) {
        asm volatile("cp.async.wait_group 0;");
        __syncthreads();
        if (kt + 1 < NKT) load_stage(kt + 1, (kt + 1) & 1);

        const float* Abase = sm + (kt & 1) * STG_FL;
        const float* Bbase = Abase + 128 * LDA;
        const float* Aw = Abase + (wm * 64) * LDA;
        const float* Bw = Bbase + (wn * 32) * LDA;

#pragma unroll
        for (int ks = 0; ks < 4; ks++) {
            const int k0 = ks * 8;
            uint32_t bf[4][2];
#pragma unroll
            for (int nt = 0; nt < 4; nt++) {
                const float* bp = Bw + (nt * 8 + g) * LDA + k0;
                bf[nt][0] = f2tf32(bp[tg]);
                bf[nt][1] = f2tf32(bp[tg + 4]);
            }
#pragma unroll
            for (int mt = 0; mt < 4; mt++) {
                const float* ap0 = Aw + (mt * 16 + g) * LDA + k0;
                const float* ap1 = ap0 + 8 * LDA;
                uint32_t a0 = f2tf32(ap0[tg]);
                uint32_t a1 = f2tf32(ap1[tg]);
                uint32_t a2 = f2tf32(ap0[tg + 4]);
                uint32_t a3 = f2tf32(ap1[tg + 4]);
#pragma unroll
                for (int nt = 0; nt < 4; nt++) {
                    asm volatile(
                        "mma.sync.aligned.m16n8k8.row.col.f32.tf32.tf32.f32 "
                        "{%0,%1,%2,%3}, {%4,%5,%6,%7}, {%8,%9}, {%0,%1,%2,%3};"
                        : "+f"(acc[mt][nt][0]), "+f"(acc[mt][nt][1]),
                          "+f"(acc[mt][nt][2]), "+f"(acc[mt][nt][3])
                        : "r"(a0), "r"(a1), "r"(a2), "r"(a3),
                          "r"(bf[nt][0]), "r"(bf[nt][1]));
                }
            }
        }
    }

    // ---- epilogue ----
#pragma unroll
    for (int mt = 0; mt < 4; mt++) {
        int r0 = bm + wm * 64 + mt * 16 + g;
        int r1 = r0 + 8;
#pragma unroll
        for (int nt = 0; nt < 4; nt++) {
            int col = bn + wn * 32 + nt * 8 + tg * 2;
            float b0 = bias[col], b1 = bias[col + 1];
            float2 o0, o1;
            o0.x = (acc[mt][nt][0] + b0) * alpha;
            o0.y = (acc[mt][nt][1] + b1) * alpha;
            o1.x = (acc[mt][nt][2] + b0) * alpha;
            o1.y = (acc[mt][nt][3] + b1) * alpha;
            if (resid) {
                o0.x += resid[(size_t)r0 * DD + col];
                o0.y += resid[(size_t)r0 * DD + col + 1];
                o1.x += resid[(size_t)r1 * DD + col];
                o1.y += resid[(size_t)r1 * DD + col + 1];
            }
            if (C) {
                *(float2*)(C + (size_t)r0 * DD + col) = o0;
                *(float2*)(C + (size_t)r1 * DD + col) = o1;
            }
            if (Cb) {
                *(__nv_bfloat162*)(Cb + (size_t)r0 * DD + col) =
                    __floats2bfloat162_rn(o0.x, o0.y);
                *(__nv_bfloat162*)(Cb + (size_t)r1 * DD + col) =
                    __floats2bfloat162_rn(o1.x, o1.y);
            }
        }
    }
}

// ---------------- CSR build ----------------
__global__ void hist_kernel(const int* __restrict__ dst)
{
    int e = blockIdx.x * blockDim.x + threadIdx.x;
    if (e < EE) atomicAdd(&g_cnt[dst[e]], 1);
}

__global__ void scan_kernel()
{
    __shared__ int sh[1024];
    int t = threadIdx.x;
    int base = t * 8;
    int loc[8];
    int s = 0;
#pragma unroll
    for (int j = 0; j < 8; j++) { loc[j] = s; s += g_cnt[base + j]; }
    sh[t] = s;
    __syncthreads();
    for (int off = 1; off < 1024; off <<= 1) {
        int v = (t >= off) ? sh[t - off] : 0;
        __syncthreads();
        sh[t] += v;
        __syncthreads();
    }
    int excl = (t > 0) ? sh[t - 1] : 0;
#pragma unroll
    for (int j = 0; j < 8; j++) {
        g_rowptr[base + j] = excl + loc[j];
        g_cursor[base + j] = excl + loc[j];
    }
    if (t == 1023) g_rowptr[NN] = excl + s;
}

__global__ void scatter_kernel(const int* __restrict__ dst)
{
    int e = blockIdx.x * blockDim.x + threadIdx.x;
    if (e < EE) {
        int p = atomicAdd(&g_cursor[dst[e]], 1);
        g_csr_eid[p] = e;
    }
}

// per-row sort by original edge id -> deterministic fp reduction order
__global__ void sort_rows_kernel(const int* __restrict__ edge_src)
{
    int n = blockIdx.x;
    int r0 = g_rowptr[n], r1 = g_rowptr[n + 1];
    int deg = r1 - r0;
    int lane = threadIdx.x;
    __shared__ int sh[2048];
    if (deg <= 2048) {
        for (int i = lane; i < deg; i += 32) sh[i] = g_csr_eid[r0 + i];
        __syncwarp();
        for (int p = 0; p < deg; p++) {
            for (int i = (p & 1) + 2 * lane; i + 1 < deg; i += 64) {
                int a = sh[i], b = sh[i + 1];
                if (a > b) { sh[i] = b; sh[i + 1] = a; }
            }
            __syncwarp();
        }
        for (int i = lane; i < deg; i += 32) {
            int e = sh[i];
            g_csr_eid[r0 + i] = e;
            g_csr_src[r0 + i] = edge_src[e];
            g_csr_dst[r0 + i] = n;
        }
    } else {
        for (int i = lane; i < deg; i += 32) {
            int e = g_csr_eid[r0 + i];
            g_csr_src[r0 + i] = edge_src[e];
            g_csr_dst[r0 + i] = n;
        }
    }
}

// ---------------- edge scores: score[i,h] = k[src]·q[dst] per head (bf16 in) ----
__global__ void score_kernel(const float* __restrict__ mask)
{
    int gw = (blockIdx.x * blockDim.x + threadIdx.x) >> 5;
    int lane = threadIdx.x & 31;
    if (gw >= EE) return;
    int src = g_csr_src[gw];
    int dst = g_csr_dst[gw];
    const __nv_bfloat162* kk = (const __nv_bfloat162*)(g_kh + (size_t)src * DD);
    const __nv_bfloat162* qq = (const __nv_bfloat162*)(g_qh + (size_t)dst * DD);
    bool m = (mask[dst] >= 0.f);
#pragma unroll
    for (int h = 0; h < HH; h++) {
        float2 a = __bfloat1622float2(kk[h * 32 + lane]);
        float2 b = __bfloat1622float2(qq[h * 32 + lane]);
        float p = a.x * b.x + a.y * b.y;
#pragma unroll
        for (int off = 16; off > 0; off >>= 1)
            p += __shfl_xor_sync(0xffffffffu, p, off);
        if (lane == 0) g_score[(size_t)gw * HH + h] = m ? p : -1e4f;
    }
}

// ---------------- per-dst softmax over incoming edges (warp/node, lane=head) ----
__global__ void softmax_kernel()
{
    int node = blockIdx.x * 4 + (threadIdx.x >> 5);
    int lane = threadIdx.x & 31;
    if (node >= NN || lane >= HH) return;
    int r0 = g_rowptr[node], r1 = g_rowptr[node + 1];
    float mx = -3.4e38f;
    for (int i = r0; i < r1; i++) mx = fmaxf(mx, g_score[(size_t)i * HH + lane]);
    float s = 0.f;
    for (int i = r0; i < r1; i++) s += expf(g_score[(size_t)i * HH + lane] - mx);
    float inv = 1.f / s;
    for (int i = r0; i < r1; i++) {
        float a = expf(g_score[(size_t)i * HH + lane] - mx) * inv;
        g_score[(size_t)i * HH + lane] = a;
    }
}

// -------- message passing: h_out = 0.9 * sum_e attn*h_in[src] + 0.1*v ----------
// hin bf16 gather; fp32 accumulate; bf16 out (+ optional fp32 out for last step)
__global__ void mp_kernel(const __nv_bfloat16* __restrict__ hin,
                          __nv_bfloat16* __restrict__ hout,
                          float* __restrict__ houtf)
{
    int n = blockIdx.x;
    int t = threadIdx.x;   // 128 threads; each owns bf162 slots t, t+128, t+256
    int r0 = g_rowptr[n], r1 = g_rowptr[n + 1];
    int h0 = t >> 5;           // head of slot t        (0..3)
    float2 a0 = {0.f, 0.f}, a1 = {0.f, 0.f}, a2 = {0.f, 0.f};
    for (int i = r0; i < r1; i++) {
        const __nv_bfloat162* hs =
            (const __nv_bfloat162*)(hin + (size_t)g_csr_src[i] * DD);
        const float* at = g_score + (size_t)i * HH;
        float w0 = at[h0], w1 = at[h0 + 4], w2 = at[h0 + 8];
        float2 x0 = __bfloat1622float2(hs[t]);
        float2 x1 = __bfloat1622float2(hs[t + 128]);
        float2 x2 = __bfloat1622float2(hs[t + 256]);
        a0.x = fmaf(w0, x0.x, a0.x); a0.y = fmaf(w0, x0.y, a0.y);
        a1.x = fmaf(w1, x1.x, a1.x); a1.y = fmaf(w1, x1.y, a1.y);
        a2.x = fmaf(w2, x2.x, a2.x); a2.y = fmaf(w2, x2.y, a2.y);
    }
    const float2* vv = (const float2*)(g_v + (size_t)n * DD);
    float2 v0 = vv[t], v1 = vv[t + 128], v2 = vv[t + 256];
    float2 o0, o1, o2;
    o0.x = 0.9f * a0.x + 0.1f * v0.x;  o0.y = 0.9f * a0.y + 0.1f * v0.y;
    o1.x = 0.9f * a1.x + 0.1f * v1.x;  o1.y = 0.9f * a1.y + 0.1f * v1.y;
    o2.x = 0.9f * a2.x + 0.1f * v2.x;  o2.y = 0.9f * a2.y + 0.1f * v2.y;
    if (hout) {
        __nv_bfloat162* ob = (__nv_bfloat162*)(hout + (size_t)n * DD);
        ob[t]       = __floats2bfloat162_rn(o0.x, o0.y);
        ob[t + 128] = __floats2bfloat162_rn(o1.x, o1.y);
        ob[t + 256] = __floats2bfloat162_rn(o2.x, o2.y);
    }
    if (houtf) {
        float2* of = (float2*)(houtf + (size_t)n * DD);
        of[t] = o0; of[t + 128] = o1; of[t + 256] = o2;
    }
}

// ---------------- residual layernorm ----------------
__global__ void layernorm_kernel(const float* __restrict__ y,
                                 const float* __restrict__ gam,
                                 const float* __restrict__ bet,
                                 float* __restrict__ out)
{
    int row = blockIdx.x;
    int t = threadIdx.x;  // 256
    const float* yr = y + (size_t)row * DD;
    float v0 = yr[t], v1 = yr[t + 256], v2 = yr[t + 512];
    __shared__ float sh[256];
    sh[t] = v0 + v1 + v2;
    __syncthreads();
    for (int o = 128; o > 0; o >>= 1) { if (t < o) sh[t] += sh[t + o]; __syncthreads(); }
    float mu = sh[0] * (1.f / 768.f);
    __syncthreads();
    float d0 = v0 - mu, d1 = v1 - mu, d2 = v2 - mu;
    sh[t] = d0 * d0 + d1 * d1 + d2 * d2;
    __syncthreads();
    for (int o = 128; o > 0; o >>= 1) { if (t < o) sh[t] += sh[t + o]; __syncthreads(); }
    float inv = rsqrtf(sh[0] * (1.f / 768.f) + 1e-12f);
    float* orow = out + (size_t)row * DD;
    orow[t]       = d0 * inv * gam[t]       + bet[t];
    orow[t + 256] = d1 * inv * gam[t + 256] + bet[t + 256];
    orow[t + 512] = d2 * inv * gam[t + 512] + bet[t + 512];
}

// ---------------- launch ----------------
extern "C" void kernel_launch(void* const* d_in, const int* in_sizes, int n_in,
                              void* d_out, int out_size)
{
    const float* x    = (const float*)d_in[0];   // hidden_states [2,4096,768]
    const float* mask = (const float*)d_in[1];   // attention_mask [2,4096]
    const int*   esrc = (const int*)d_in[2];
    const int*   edst = (const int*)d_in[3];
    const float* Wq = (const float*)d_in[4];  const float* bq = (const float*)d_in[5];
    const float* Wk = (const float*)d_in[6];  const float* bk = (const float*)d_in[7];
    const float* Wv = (const float*)d_in[8];  const float* bv = (const float*)d_in[9];
    const float* Wo = (const float*)d_in[10]; const float* bo = (const float*)d_in[11];
    const float* lg = (const float*)d_in[12]; const float* lb = (const float*)d_in[13];
    float* out = (float*)d_out;

    float *vp, *hfp, *yp;
    __nv_bfloat16 *qhp, *khp, *vhp, *hb0p, *hb1p;
    int* cntp;
    cudaGetSymbolAddress((void**)&vp,   g_v);
    cudaGetSymbolAddress((void**)&hfp,  g_hf);
    cudaGetSymbolAddress((void**)&yp,   g_y);
    cudaGetSymbolAddress((void**)&qhp,  g_qh);
    cudaGetSymbolAddress((void**)&khp,  g_kh);
    cudaGetSymbolAddress((void**)&vhp,  g_vh);
    cudaGetSymbolAddress((void**)&hb0p, g_hb0);
    cudaGetSymbolAddress((void**)&hb1p, g_hb1);
    cudaGetSymbolAddress((void**)&cntp, g_cnt);

    cudaFuncSetAttribute(gemm_tf32, cudaFuncAttributeMaxDynamicSharedMemorySize, GEMM_SMEM);

    dim3 ggrid(DD / 128, NN / 128);   // (6, 64)

    // q,k -> bf16 only; v -> fp32 (mix) + bf16 (first gather)
    gemm_tf32<<<ggrid, 256, GEMM_SMEM>>>(x, Wq, bq, nullptr, nullptr, qhp, 0.125f);
    gemm_tf32<<<ggrid, 256, GEMM_SMEM>>>(x, Wk, bk, nullptr, nullptr, khp, 1.0f);
    gemm_tf32<<<ggrid, 256, GEMM_SMEM>>>(x, Wv, bv, nullptr, vp, vhp, 1.0f);

    // CSR build (deterministic: per-row sort by edge id)
    cudaMemsetAsync(cntp, 0, NN * sizeof(int), 0);
    hist_kernel<<<(EE + 255) / 256, 256>>>(edst);
    scan_kernel<<<1, 1024>>>();
    scatter_kernel<<<(EE + 255) / 256, 256>>>(edst);
    sort_rows_kernel<<<NN, 32>>>(esrc);

    // edge scores + per-dst softmax
    score_kernel<<<EE / 8, 256>>>(mask);
    softmax_kernel<<<NN / 4, 128>>>();

    // 5 message-passing steps (bf16 ping-pong; last emits fp32 for Wo GEMM)
    mp_kernel<<<NN, 128>>>(vhp,  hb0p, nullptr);
    mp_kernel<<<NN, 128>>>(hb0p, hb1p, nullptr);
    mp_kernel<<<NN, 128>>>(hb1p, hb0p, nullptr);
    mp_kernel<<<NN, 128>>>(hb0p, hb1p, nullptr);
    mp_kernel<<<NN, 128>>>(hb1p, nullptr, hfp);

    // output projection + residual, then layernorm
    gemm_tf32<<<ggrid, 256, GEMM_SMEM>>>(hfp, Wo, bo, x, yp, nullptr, 1.0f);
    layernorm_kernel<<<NN, 256>>>(yp, lg, lb, out);
}

// round 6
// speedup vs baseline: 2.9057x; 1.3253x over previous
#include <cuda_runtime.h>
#include <cuda_bf16.h>
#include <cstdint>
#include <math.h>

// Problem constants
#define NN   8192          // B*S nodes
#define DD   768           // hidden dim
#define EE   131072        // edges
#define HH   12            // heads
#define HDD  64            // head dim

// ---------------- scratch (static device globals; no allocation) ----------------
__device__ float g_v[NN * DD];             // v fp32 (mix term)
__device__ float g_y[NN * DD];
__device__ __nv_bfloat16 g_xh[NN * DD];    // hidden_states bf16 (GEMM A input)
__device__ __nv_bfloat16 g_wh[4 * DD * DD];// Wq,Wk,Wv,Wo bf16
__device__ __nv_bfloat16 g_qh[NN * DD];    // q (bf16, pre-scaled)
__device__ __nv_bfloat16 g_kh[NN * DD];    // k (bf16)
__device__ __nv_bfloat16 g_vh[NN * DD];    // v (bf16, mp step-1 gather input)
__device__ __nv_bfloat16 g_hb0[NN * DD];   // h ping (bf16)
__device__ __nv_bfloat16 g_hb1[NN * DD];   // h pong (bf16)
__device__ float g_score[EE * HH];         // scores, then attn in-place
__device__ int   g_cnt[NN];
__device__ int   g_rowptr[NN + 1];
__device__ int   g_cursor[NN];
__device__ int   g_csr_eid[EE];
__device__ int   g_csr_src[EE];
__device__ int   g_csr_dst[EE];

__device__ __forceinline__ uint32_t smem_cast(const void* p) {
    return (uint32_t)__cvta_generic_to_shared(p);
}

// ---------------- fp32 -> bf16 conversion (vectorized) ----------------
__global__ void cvt_bf16_kernel(const float4* __restrict__ src,
                                __nv_bfloat162* __restrict__ dst, int n4)
{
    int i = blockIdx.x * blockDim.x + threadIdx.x;
    if (i < n4) {
        float4 v = src[i];
        dst[2 * i]     = __floats2bfloat162_rn(v.x, v.y);
        dst[2 * i + 1] = __floats2bfloat162_rn(v.z, v.w);
    }
}

// ================= bf16 warp-MMA GEMM (m16n8k16) =====
// C = (A @ W^T + bias)*alpha (+resid); optional fp32 C and/or bf16 Cb outputs.
// A [M,768] bf16 row-major, W [768,768] bf16 row-major (NT GEMM).

#define BKK    32                        // k-step (bf16 elems)
#define LDH    40                        // 32 + 8 pad bf16 per row
#define STG_H  (128 * LDH * 2)           // bf16 elems per stage (A + B)
#define GEMM_SMEM (2 * STG_H * 2)        // bytes = 40960

__global__ __launch_bounds__(256, 2)
void gemm_bf16(const __nv_bfloat16* __restrict__ A, const __nv_bfloat16* __restrict__ W,
               const float* __restrict__ bias, const float* __restrict__ resid,
               float* __restrict__ C, __nv_bfloat16* __restrict__ Cb, float alpha)
{
    extern __shared__ __nv_bfloat16 smh[];
    const int tid  = threadIdx.x;
    const int wid  = tid >> 5;
    const int lane = tid & 31;
    const int g    = lane >> 2;        // 0..7
    const int tg   = lane & 3;         // 0..3
    const int wm   = wid >> 2;         // 0..1  (64 rows each)
    const int wn   = wid & 3;          // 0..3  (32 cols each)
    const int bm   = blockIdx.y * 128;
    const int bn   = blockIdx.x * 128;

    const __nv_bfloat16* Ab = A + (size_t)bm * DD;
    const __nv_bfloat16* Wb = W + (size_t)bn * DD;

    float acc[4][4][4];
#pragma unroll
    for (int mt = 0; mt < 4; mt++)
#pragma unroll
        for (int nt = 0; nt < 4; nt++)
#pragma unroll
            for (int c = 0; c < 4; c++) acc[mt][nt][c] = 0.f;

    // stage loader: 128 rows x 32 bf16 (64B = 4x16B chunks) for A and B
    auto load_stage = [&](int kt, int stg) {
        __nv_bfloat16* Abase = smh + stg * STG_H;
        __nv_bfloat16* Bbase = Abase + 128 * LDH;
#pragma unroll
        for (int i = 0; i < 2; i++) {
            int idx = tid + i * 256;          // 0..511 chunks
            int row = idx >> 2;
            int c16 = idx & 3;
            const __nv_bfloat16* ga = Ab + (size_t)row * DD + kt * BKK + c16 * 8;
            const __nv_bfloat16* gb = Wb + (size_t)row * DD + kt * BKK + c16 * 8;
            uint32_t da = smem_cast(Abase + row * LDH + c16 * 8);
            uint32_t db = smem_cast(Bbase + row * LDH + c16 * 8);
            asm volatile("cp.async.cg.shared.global [%0], [%1], 16;" :: "r"(da), "l"(ga));
            asm volatile("cp.async.cg.shared.global [%0], [%1], 16;" :: "r"(db), "l"(gb));
        }
        asm volatile("cp.async.commit_group;");
    };

    load_stage(0, 0);

    const int NKT = DD / BKK;   // 24
    for (int kt = 0; kt < NKT; kt++) {
        asm volatile("cp.async.wait_group 0;");
        __syncthreads();
        if (kt + 1 < NKT) load_stage(kt + 1, (kt + 1) & 1);

        const __nv_bfloat16* Abase = smh + (kt & 1) * STG_H;
        const __nv_bfloat16* Bbase = Abase + 128 * LDH;
        const __nv_bfloat16* Aw = Abase + (wm * 64) * LDH;
        const __nv_bfloat16* Bw = Bbase + (wn * 32) * LDH;

#pragma unroll
        for (int ks = 0; ks < 2; ks++) {        // two k16 sub-steps per 32-chunk
            const int k0 = ks * 16;
            uint32_t bf[4][2];
#pragma unroll
            for (int nt = 0; nt < 4; nt++) {
                const __nv_bfloat16* bp = Bw + (nt * 8 + g) * LDH + k0;
                bf[nt][0] = *(const uint32_t*)(bp + 2 * tg);
                bf[nt][1] = *(const uint32_t*)(bp + 2 * tg + 8);
            }
#pragma unroll
            for (int mt = 0; mt < 4; mt++) {
                const __nv_bfloat16* ap0 = Aw + (mt * 16 + g) * LDH + k0;
                const __nv_bfloat16* ap1 = ap0 + 8 * LDH;
                uint32_t a0 = *(const uint32_t*)(ap0 + 2 * tg);
                uint32_t a1 = *(const uint32_t*)(ap1 + 2 * tg);
                uint32_t a2 = *(const uint32_t*)(ap0 + 2 * tg + 8);
                uint32_t a3 = *(const uint32_t*)(ap1 + 2 * tg + 8);
#pragma unroll
                for (int nt = 0; nt < 4; nt++) {
                    asm volatile(
                        "mma.sync.aligned.m16n8k16.row.col.f32.bf16.bf16.f32 "
                        "{%0,%1,%2,%3}, {%4,%5,%6,%7}, {%8,%9}, {%0,%1,%2,%3};"
                        : "+f"(acc[mt][nt][0]), "+f"(acc[mt][nt][1]),
                          "+f"(acc[mt][nt][2]), "+f"(acc[mt][nt][3])
                        : "r"(a0), "r"(a1), "r"(a2), "r"(a3),
                          "r"(bf[nt][0]), "r"(bf[nt][1]));
                }
            }
        }
    }

    // ---- epilogue ----
#pragma unroll
    for (int mt = 0; mt < 4; mt++) {
        int r0 = bm + wm * 64 + mt * 16 + g;
        int r1 = r0 + 8;
#pragma unroll
        for (int nt = 0; nt < 4; nt++) {
            int col = bn + wn * 32 + nt * 8 + tg * 2;
            float b0 = bias[col], b1 = bias[col + 1];
            float2 o0, o1;
            o0.x = (acc[mt][nt][0] + b0) * alpha;
            o0.y = (acc[mt][nt][1] + b1) * alpha;
            o1.x = (acc[mt][nt][2] + b0) * alpha;
            o1.y = (acc[mt][nt][3] + b1) * alpha;
            if (resid) {
                o0.x += resid[(size_t)r0 * DD + col];
                o0.y += resid[(size_t)r0 * DD + col + 1];
                o1.x += resid[(size_t)r1 * DD + col];
                o1.y += resid[(size_t)r1 * DD + col + 1];
            }
            if (C) {
                *(float2*)(C + (size_t)r0 * DD + col) = o0;
                *(float2*)(C + (size_t)r1 * DD + col) = o1;
            }
            if (Cb) {
                *(__nv_bfloat162*)(Cb + (size_t)r0 * DD + col) =
                    __floats2bfloat162_rn(o0.x, o0.y);
                *(__nv_bfloat162*)(Cb + (size_t)r1 * DD + col) =
                    __floats2bfloat162_rn(o1.x, o1.y);
            }
        }
    }
}

// ---------------- CSR build ----------------
__global__ void hist_kernel(const int* __restrict__ dst)
{
    int e = blockIdx.x * blockDim.x + threadIdx.x;
    if (e < EE) atomicAdd(&g_cnt[dst[e]], 1);
}

__global__ void scan_kernel()
{
    __shared__ int sh[1024];
    int t = threadIdx.x;
    int base = t * 8;
    int loc[8];
    int s = 0;
#pragma unroll
    for (int j = 0; j < 8; j++) { loc[j] = s; s += g_cnt[base + j]; }
    sh[t] = s;
    __syncthreads();
    for (int off = 1; off < 1024; off <<= 1) {
        int v = (t >= off) ? sh[t - off] : 0;
        __syncthreads();
        sh[t] += v;
        __syncthreads();
    }
    int excl = (t > 0) ? sh[t - 1] : 0;
#pragma unroll
    for (int j = 0; j < 8; j++) {
        g_rowptr[base + j] = excl + loc[j];
        g_cursor[base + j] = excl + loc[j];
    }
    if (t == 1023) g_rowptr[NN] = excl + s;
}

__global__ void scatter_kernel(const int* __restrict__ dst)
{
    int e = blockIdx.x * blockDim.x + threadIdx.x;
    if (e < EE) {
        int p = atomicAdd(&g_cursor[dst[e]], 1);
        g_csr_eid[p] = e;
    }
}

// per-row sort by original edge id -> deterministic fp reduction order
__global__ void sort_rows_kernel(const int* __restrict__ edge_src)
{
    int n = blockIdx.x;
    int r0 = g_rowptr[n], r1 = g_rowptr[n + 1];
    int deg = r1 - r0;
    int lane = threadIdx.x;
    __shared__ int sh[2048];
    if (deg <= 2048) {
        for (int i = lane; i < deg; i += 32) sh[i] = g_csr_eid[r0 + i];
        __syncwarp();
        for (int p = 0; p < deg; p++) {
            for (int i = (p & 1) + 2 * lane; i + 1 < deg; i += 64) {
                int a = sh[i], b = sh[i + 1];
                if (a > b) { sh[i] = b; sh[i + 1] = a; }
            }
            __syncwarp();
        }
        for (int i = lane; i < deg; i += 32) {
            int e = sh[i];
            g_csr_eid[r0 + i] = e;
            g_csr_src[r0 + i] = edge_src[e];
            g_csr_dst[r0 + i] = n;
        }
    } else {
        for (int i = lane; i < deg; i += 32) {
            int e = g_csr_eid[r0 + i];
            g_csr_src[r0 + i] = edge_src[e];
            g_csr_dst[r0 + i] = n;
        }
    }
}

// ---------------- edge scores: score[i,h] = k[src]·q[dst] per head (bf16 in) ----
__global__ void score_kernel(const float* __restrict__ mask)
{
    int gw = (blockIdx.x * blockDim.x + threadIdx.x) >> 5;
    int lane = threadIdx.x & 31;
    if (gw >= EE) return;
    int src = g_csr_src[gw];
    int dst = g_csr_dst[gw];
    const __nv_bfloat162* kk = (const __nv_bfloat162*)(g_kh + (size_t)src * DD);
    const __nv_bfloat162* qq = (const __nv_bfloat162*)(g_qh + (size_t)dst * DD);
    bool m = (mask[dst] >= 0.f);
#pragma unroll
    for (int h = 0; h < HH; h++) {
        float2 a = __bfloat1622float2(kk[h * 32 + lane]);
        float2 b = __bfloat1622float2(qq[h * 32 + lane]);
        float p = a.x * b.x + a.y * b.y;
#pragma unroll
        for (int off = 16; off > 0; off >>= 1)
            p += __shfl_xor_sync(0xffffffffu, p, off);
        if (lane == 0) g_score[(size_t)gw * HH + h] = m ? p : -1e4f;
    }
}

// ---------------- per-dst softmax over incoming edges (warp/node, lane=head) ----
__global__ void softmax_kernel()
{
    int node = blockIdx.x * 4 + (threadIdx.x >> 5);
    int lane = threadIdx.x & 31;
    if (node >= NN || lane >= HH) return;
    int r0 = g_rowptr[node], r1 = g_rowptr[node + 1];
    float mx = -3.4e38f;
    for (int i = r0; i < r1; i++) mx = fmaxf(mx, g_score[(size_t)i * HH + lane]);
    float s = 0.f;
    for (int i = r0; i < r1; i++) s += expf(g_score[(size_t)i * HH + lane] - mx);
    float inv = 1.f / s;
    for (int i = r0; i < r1; i++) {
        float a = expf(g_score[(size_t)i * HH + lane] - mx) * inv;
        g_score[(size_t)i * HH + lane] = a;
    }
}

// -------- message passing: h_out = 0.9 * sum_e attn*h_in[src] + 0.1*v ----------
__global__ void mp_kernel(const __nv_bfloat16* __restrict__ hin,
                          __nv_bfloat16* __restrict__ hout,
                          float* __restrict__ houtf)
{
    int n = blockIdx.x;
    int t = threadIdx.x;   // 128 threads; bf162 slots t, t+128, t+256
    int r0 = g_rowptr[n], r1 = g_rowptr[n + 1];
    int h0 = t >> 5;           // 0..3
    float2 a0 = {0.f, 0.f}, a1 = {0.f, 0.f}, a2 = {0.f, 0.f};
    for (int i = r0; i < r1; i++) {
        const __nv_bfloat162* hs =
            (const __nv_bfloat162*)(hin + (size_t)g_csr_src[i] * DD);
        const float* at = g_score + (size_t)i * HH;
        float w0 = at[h0], w1 = at[h0 + 4], w2 = at[h0 + 8];
        float2 x0 = __bfloat1622float2(hs[t]);
        float2 x1 = __bfloat1622float2(hs[t + 128]);
        float2 x2 = __bfloat1622float2(hs[t + 256]);
        a0.x = fmaf(w0, x0.x, a0.x); a0.y = fmaf(w0, x0.y, a0.y);
        a1.x = fmaf(w1, x1.x, a1.x); a1.y = fmaf(w1, x1.y, a1.y);
        a2.x = fmaf(w2, x2.x, a2.x); a2.y = fmaf(w2, x2.y, a2.y);
    }
    const float2* vv = (const float2*)(g_v + (size_t)n * DD);
    float2 v0 = vv[t], v1 = vv[t + 128], v2 = vv[t + 256];
    float2 o0, o1, o2;
    o0.x = 0.9f * a0.x + 0.1f * v0.x;  o0.y = 0.9f * a0.y + 0.1f * v0.y;
    o1.x = 0.9f * a1.x + 0.1f * v1.x;  o1.y = 0.9f * a1.y + 0.1f * v1.y;
    o2.x = 0.9f * a2.x + 0.1f * v2.x;  o2.y = 0.9f * a2.y + 0.1f * v2.y;
    if (hout) {
        __nv_bfloat162* ob = (__nv_bfloat162*)(hout + (size_t)n * DD);
        ob[t]       = __floats2bfloat162_rn(o0.x, o0.y);
        ob[t + 128] = __floats2bfloat162_rn(o1.x, o1.y);
        ob[t + 256] = __floats2bfloat162_rn(o2.x, o2.y);
    }
    if (houtf) {
        float2* of = (float2*)(houtf + (size_t)n * DD);
        of[t] = o0; of[t + 128] = o1; of[t + 256] = o2;
    }
}

// ---------------- residual layernorm ----------------
__global__ void layernorm_kernel(const float* __restrict__ y,
                                 const float* __restrict__ gam,
                                 const float* __restrict__ bet,
                                 float* __restrict__ out)
{
    int row = blockIdx.x;
    int t = threadIdx.x;  // 256
    const float* yr = y + (size_t)row * DD;
    float v0 = yr[t], v1 = yr[t + 256], v2 = yr[t + 512];
    __shared__ float sh[256];
    sh[t] = v0 + v1 + v2;
    __syncthreads();
    for (int o = 128; o > 0; o >>= 1) { if (t < o) sh[t] += sh[t + o]; __syncthreads(); }
    float mu = sh[0] * (1.f / 768.f);
    __syncthreads();
    float d0 = v0 - mu, d1 = v1 - mu, d2 = v2 - mu;
    sh[t] = d0 * d0 + d1 * d1 + d2 * d2;
    __syncthreads();
    for (int o = 128; o > 0; o >>= 1) { if (t < o) sh[t] += sh[t + o]; __syncthreads(); }
    float inv = rsqrtf(sh[0] * (1.f / 768.f) + 1e-12f);
    float* orow = out + (size_t)row * DD;
    orow[t]       = d0 * inv * gam[t]       + bet[t];
    orow[t + 256] = d1 * inv * gam[t + 256] + bet[t + 256];
    orow[t + 512] = d2 * inv * gam[t + 512] + bet[t + 512];
}

// ---------------- launch ----------------
extern "C" void kernel_launch(void* const* d_in, const int* in_sizes, int n_in,
                              void* d_out, int out_size)
{
    const float* x    = (const float*)d_in[0];
    const float* mask = (const float*)d_in[1];
    const int*   esrc = (const int*)d_in[2];
    const int*   edst = (const int*)d_in[3];
    const float* Wq = (const float*)d_in[4];  const float* bq = (const float*)d_in[5];
    const float* Wk = (const float*)d_in[6];  const float* bk = (const float*)d_in[7];
    const float* Wv = (const float*)d_in[8];  const float* bv = (const float*)d_in[9];
    const float* Wo = (const float*)d_in[10]; const float* bo = (const float*)d_in[11];
    const float* lg = (const float*)d_in[12]; const float* lb = (const float*)d_in[13];
    float* out = (float*)d_out;

    float *vp, *yp;
    __nv_bfloat16 *xhp, *whp, *qhp, *khp, *vhp, *hb0p, *hb1p;
    int* cntp;
    cudaGetSymbolAddress((void**)&vp,   g_v);
    cudaGetSymbolAddress((void**)&yp,   g_y);
    cudaGetSymbolAddress((void**)&xhp,  g_xh);
    cudaGetSymbolAddress((void**)&whp,  g_wh);
    cudaGetSymbolAddress((void**)&qhp,  g_qh);
    cudaGetSymbolAddress((void**)&khp,  g_kh);
    cudaGetSymbolAddress((void**)&vhp,  g_vh);
    cudaGetSymbolAddress((void**)&hb0p, g_hb0);
    cudaGetSymbolAddress((void**)&hb1p, g_hb1);
    cudaGetSymbolAddress((void**)&cntp, g_cnt);

    __nv_bfloat16* wqh = whp;
    __nv_bfloat16* wkh = whp + (size_t)DD * DD;
    __nv_bfloat16* wvh = whp + 2 * (size_t)DD * DD;
    __nv_bfloat16* woh = whp + 3 * (size_t)DD * DD;

    cudaFuncSetAttribute(gemm_bf16, cudaFuncAttributeMaxDynamicSharedMemorySize, GEMM_SMEM);

    // ---- fp32 -> bf16 conversions (x and the four weights) ----
    {
        int n4 = NN * DD / 4;
        cvt_bf16_kernel<<<(n4 + 255) / 256, 256>>>((const float4*)x, (__nv_bfloat162*)xhp, n4);
        int w4 = DD * DD / 4;
        cvt_bf16_kernel<<<(w4 + 255) / 256, 256>>>((const float4*)Wq, (__nv_bfloat162*)wqh, w4);
        cvt_bf16_kernel<<<(w4 + 255) / 256, 256>>>((const float4*)Wk, (__nv_bfloat162*)wkh, w4);
        cvt_bf16_kernel<<<(w4 + 255) / 256, 256>>>((const float4*)Wv, (__nv_bfloat162*)wvh, w4);
        cvt_bf16_kernel<<<(w4 + 255) / 256, 256>>>((const float4*)Wo, (__nv_bfloat162*)woh, w4);
    }

    dim3 ggrid(DD / 128, NN / 128);   // (6, 64)

    // q,k -> bf16 only; v -> fp32 (mix) + bf16 (first gather)
    gemm_bf16<<<ggrid, 256, GEMM_SMEM>>>(xhp, wqh, bq, nullptr, nullptr, qhp, 0.125f);
    gemm_bf16<<<ggrid, 256, GEMM_SMEM>>>(xhp, wkh, bk, nullptr, nullptr, khp, 1.0f);
    gemm_bf16<<<ggrid, 256, GEMM_SMEM>>>(xhp, wvh, bv, nullptr, vp, vhp, 1.0f);

    // CSR build (deterministic: per-row sort by edge id)
    cudaMemsetAsync(cntp, 0, NN * sizeof(int), 0);
    hist_kernel<<<(EE + 255) / 256, 256>>>(edst);
    scan_kernel<<<1, 1024>>>();
    scatter_kernel<<<(EE + 255) / 256, 256>>>(edst);
    sort_rows_kernel<<<NN, 32>>>(esrc);

    // edge scores + per-dst softmax
    score_kernel<<<EE / 8, 256>>>(mask);
    softmax_kernel<<<NN / 4, 128>>>();

    // 5 message-passing steps (bf16 ping-pong; last emits bf16 h for Wo GEMM)
    mp_kernel<<<NN, 128>>>(vhp,  hb0p, nullptr);
    mp_kernel<<<NN, 128>>>(hb0p, hb1p, nullptr);
    mp_kernel<<<NN, 128>>>(hb1p, hb0p, nullptr);
    mp_kernel<<<NN, 128>>>(hb0p, hb1p, nullptr);
    mp_kernel<<<NN, 128>>>(hb1p, hb0p, nullptr);

    // output projection + residual (A = bf16 h), then layernorm
    gemm_bf16<<<ggrid, 256, GEMM_SMEM>>>(hb0p, woh, bo, x, yp, nullptr, 1.0f);
    layernorm_kernel<<<NN, 256>>>(yp, lg, lb, out);
}

// round 9
// speedup vs baseline: 3.1167x; 1.0726x over previous
#include <cuda_runtime.h>
#include <cuda_bf16.h>
#include <cstdint>
#include <math.h>

// Problem constants
#define NN   8192          // B*S nodes
#define DD   768           // hidden dim
#define EE   131072        // edges
#define HH   12            // heads
#define HDD  64            // head dim

// ---------------- scratch (static device globals; no allocation) ----------------
__device__ float g_v[NN * DD];             // v fp32 (mix term)
__device__ float g_y[NN * DD];
__device__ __nv_bfloat16 g_xh[NN * DD];    // hidden_states bf16 (GEMM A input)
__device__ __nv_bfloat16 g_wh[4 * DD * DD];// Wq,Wk,Wv,Wo bf16
__device__ __nv_bfloat16 g_qh[NN * DD];    // q (bf16, pre-scaled)
__device__ __nv_bfloat16 g_kh[NN * DD];    // k (bf16)
__device__ __nv_bfloat16 g_vh[NN * DD];    // v (bf16, mp step-1 gather input)
__device__ __nv_bfloat16 g_hb0[NN * DD];   // h ping (bf16)
__device__ __nv_bfloat16 g_hb1[NN * DD];   // h pong (bf16)
__device__ float g_score[EE * HH];         // attn weights (written by fused kernel)
__device__ int   g_cnt[NN];
__device__ int   g_rowptr[NN + 1];
__device__ int   g_cursor[NN];
__device__ int   g_csr_eid[EE];
__device__ int   g_csr_src[EE];

__device__ __forceinline__ uint32_t smem_cast(const void* p) {
    return (uint32_t)__cvta_generic_to_shared(p);
}

// ---------------- fp32 -> bf16 conversion (vectorized) ----------------
__global__ void cvt_bf16_kernel(const float4* __restrict__ src,
                                __nv_bfloat162* __restrict__ dst, int n4)
{
    int i = blockIdx.x * blockDim.x + threadIdx.x;
    if (i < n4) {
        float4 v = src[i];
        dst[2 * i]     = __floats2bfloat162_rn(v.x, v.y);
        dst[2 * i + 1] = __floats2bfloat162_rn(v.z, v.w);
    }
}

// ================= bf16 warp-MMA GEMM (m16n8k16, ldmatrix A) =====
#define BKK    32                        // k-step (bf16 elems)
#define LDH    40                        // 32 + 8 pad bf16 per row
#define STG_H  (128 * LDH * 2)           // bf16 elems per stage (A + B)
#define GEMM_SMEM (2 * STG_H * 2)        // bytes = 40960

__global__ __launch_bounds__(256, 2)
void gemm_bf16(const __nv_bfloat16* __restrict__ A, const __nv_bfloat16* __restrict__ W,
               const float* __restrict__ bias, const float* __restrict__ resid,
               float* __restrict__ C, __nv_bfloat16* __restrict__ Cb, float alpha)
{
    extern __shared__ __nv_bfloat16 smh[];
    const int tid  = threadIdx.x;
    const int wid  = tid >> 5;
    const int lane = tid & 31;
    const int g    = lane >> 2;        // 0..7
    const int tg   = lane & 3;         // 0..3
    const int wm   = wid >> 2;         // 0..1  (64 rows each)
    const int wn   = wid & 3;          // 0..3  (32 cols each)
    const int bm   = blockIdx.y * 128;
    const int bn   = blockIdx.x * 128;

    const __nv_bfloat16* Ab = A + (size_t)bm * DD;
    const __nv_bfloat16* Wb = W + (size_t)bn * DD;

    float acc[4][4][4];
#pragma unroll
    for (int mt = 0; mt < 4; mt++)
#pragma unroll
        for (int nt = 0; nt < 4; nt++)
#pragma unroll
            for (int c = 0; c < 4; c++) acc[mt][nt][c] = 0.f;

    auto load_stage = [&](int kt, int stg) {
        __nv_bfloat16* Abase = smh + stg * STG_H;
        __nv_bfloat16* Bbase = Abase + 128 * LDH;
#pragma unroll
        for (int i = 0; i < 2; i++) {
            int idx = tid + i * 256;          // 0..511 chunks of 16B
            int row = idx >> 2;
            int c16 = idx & 3;
            const __nv_bfloat16* ga = Ab + (size_t)row * DD + kt * BKK + c16 * 8;
            const __nv_bfloat16* gb = Wb + (size_t)row * DD + kt * BKK + c16 * 8;
            uint32_t da = smem_cast(Abase + row * LDH + c16 * 8);
            uint32_t db = smem_cast(Bbase + row * LDH + c16 * 8);
            asm volatile("cp.async.cg.shared.global [%0], [%1], 16;" :: "r"(da), "l"(ga));
            asm volatile("cp.async.cg.shared.global [%0], [%1], 16;" :: "r"(db), "l"(gb));
        }
        asm volatile("cp.async.commit_group;");
    };

    load_stage(0, 0);

    // ldmatrix A lane mapping: row = lane&15, k-half = lane>>4
    const int lm_row = lane & 15;
    const int lm_kh  = (lane >> 4) * 8;

    const int NKT = DD / BKK;   // 24
    for (int kt = 0; kt < NKT; kt++) {
        asm volatile("cp.async.wait_group 0;");
        __syncthreads();
        if (kt + 1 < NKT) load_stage(kt + 1, (kt + 1) & 1);

        const __nv_bfloat16* Abase = smh + (kt & 1) * STG_H;
        const __nv_bfloat16* Bbase = Abase + 128 * LDH;
        const __nv_bfloat16* Aw = Abase + (wm * 64) * LDH;
        const __nv_bfloat16* Bw = Bbase + (wn * 32) * LDH;

#pragma unroll
        for (int ks = 0; ks < 2; ks++) {        // two k16 sub-steps
            const int k0 = ks * 16;
            uint32_t bf[4][2];
#pragma unroll
            for (int nt = 0; nt < 4; nt++) {
                const __nv_bfloat16* bp = Bw + (nt * 8 + g) * LDH + k0;
                bf[nt][0] = *(const uint32_t*)(bp + 2 * tg);
                bf[nt][1] = *(const uint32_t*)(bp + 2 * tg + 8);
            }
#pragma unroll
            for (int mt = 0; mt < 4; mt++) {
                uint32_t a0, a1, a2, a3;
                uint32_t addr = smem_cast(Aw + (mt * 16 + lm_row) * LDH + k0 + lm_kh);
                asm volatile(
                    "ldmatrix.sync.aligned.m8n8.x4.shared.b16 {%0,%1,%2,%3}, [%4];"
                    : "=r"(a0), "=r"(a1), "=r"(a2), "=r"(a3) : "r"(addr));
#pragma unroll
                for (int nt = 0; nt < 4; nt++) {
                    asm volatile(
                        "mma.sync.aligned.m16n8k16.row.col.f32.bf16.bf16.f32 "
                        "{%0,%1,%2,%3}, {%4,%5,%6,%7}, {%8,%9}, {%0,%1,%2,%3};"
                        : "+f"(acc[mt][nt][0]), "+f"(acc[mt][nt][1]),
                          "+f"(acc[mt][nt][2]), "+f"(acc[mt][nt][3])
                        : "r"(a0), "r"(a1), "r"(a2), "r"(a3),
                          "r"(bf[nt][0]), "r"(bf[nt][1]));
                }
            }
        }
    }

    // ---- epilogue ----
#pragma unroll
    for (int mt = 0; mt < 4; mt++) {
        int r0 = bm + wm * 64 + mt * 16 + g;
        int r1 = r0 + 8;
#pragma unroll
        for (int nt = 0; nt < 4; nt++) {
            int col = bn + wn * 32 + nt * 8 + tg * 2;
            float b0 = bias[col], b1 = bias[col + 1];
            float2 o0, o1;
            o0.x = (acc[mt][nt][0] + b0) * alpha;
            o0.y = (acc[mt][nt][1] + b1) * alpha;
            o1.x = (acc[mt][nt][2] + b0) * alpha;
            o1.y = (acc[mt][nt][3] + b1) * alpha;
            if (resid) {
                o0.x += resid[(size_t)r0 * DD + col];
                o0.y += resid[(size_t)r0 * DD + col + 1];
                o1.x += resid[(size_t)r1 * DD + col];
                o1.y += resid[(size_t)r1 * DD + col + 1];
            }
            if (C) {
                *(float2*)(C + (size_t)r0 * DD + col) = o0;
                *(float2*)(C + (size_t)r1 * DD + col) = o1;
            }
            if (Cb) {
                *(__nv_bfloat162*)(Cb + (size_t)r0 * DD + col) =
                    __floats2bfloat162_rn(o0.x, o0.y);
                *(__nv_bfloat162*)(Cb + (size_t)r1 * DD + col) =
                    __floats2bfloat162_rn(o1.x, o1.y);
            }
        }
    }
}

// ---------------- CSR build ----------------
__global__ void hist_kernel(const int* __restrict__ dst)
{
    int e = blockIdx.x * blockDim.x + threadIdx.x;
    if (e < EE) atomicAdd(&g_cnt[dst[e]], 1);
}

__global__ void scan_kernel()
{
    __shared__ int sh[1024];
    int t = threadIdx.x;
    int base = t * 8;
    int loc[8];
    int s = 0;
#pragma unroll
    for (int j = 0; j < 8; j++) { loc[j] = s; s += g_cnt[base + j]; }
    sh[t] = s;
    __syncthreads();
    for (int off = 1; off < 1024; off <<= 1) {
        int v = (t >= off) ? sh[t - off] : 0;
        __syncthreads();
        sh[t] += v;
        __syncthreads();
    }
    int excl = (t > 0) ? sh[t - 1] : 0;
#pragma unroll
    for (int j = 0; j < 8; j++) {
        g_rowptr[base + j] = excl + loc[j];
        g_cursor[base + j] = excl + loc[j];
    }
    if (t == 1023) g_rowptr[NN] = excl + s;
}

__global__ void scatter_kernel(const int* __restrict__ dst)
{
    int e = blockIdx.x * blockDim.x + threadIdx.x;
    if (e < EE) {
        int p = atomicAdd(&g_cursor[dst[e]], 1);
        g_csr_eid[p] = e;
    }
}

// per-row sort by original edge id -> deterministic fp reduction order
__global__ void sort_rows_kernel(const int* __restrict__ edge_src)
{
    int n = blockIdx.x;
    int r0 = g_rowptr[n], r1 = g_rowptr[n + 1];
    int deg = r1 - r0;
    int lane = threadIdx.x;
    __shared__ int sh[2048];
    if (deg <= 2048) {
        for (int i = lane; i < deg; i += 32) sh[i] = g_csr_eid[r0 + i];
        __syncwarp();
        for (int p = 0; p < deg; p++) {
            for (int i = (p & 1) + 2 * lane; i + 1 < deg; i += 64) {
                int a = sh[i], b = sh[i + 1];
                if (a > b) { sh[i] = b; sh[i + 1] = a; }
            }
            __syncwarp();
        }
        for (int i = lane; i < deg; i += 32) {
            int e = sh[i];
            g_csr_eid[r0 + i] = e;
            g_csr_src[r0 + i] = edge_src[e];
        }
    } else {
        for (int i = lane; i < deg; i += 32) {
            int e = g_csr_eid[r0 + i];
            g_csr_src[r0 + i] = edge_src[e];
        }
    }
}

// ====== fused edge-score + softmax: warp per dst node, q in registers ======
#define SCAP 128
__global__ __launch_bounds__(256)
void score_softmax_kernel(const float* __restrict__ mask)
{
    __shared__ float sbuf[8][SCAP * HH];   // 48 KB
    int w = threadIdx.x >> 5;
    int lane = threadIdx.x & 31;
    int node = blockIdx.x * 8 + w;
    int r0 = g_rowptr[node], r1 = g_rowptr[node + 1];
    int deg = r1 - r0;
    bool m = (mask[node] >= 0.f);

    const __nv_bfloat162* qq = (const __nv_bfloat162*)(g_qh + (size_t)node * DD);
    float2 q2[HH];
#pragma unroll
    for (int h = 0; h < HH; h++) q2[h] = __bfloat1622float2(qq[h * 32 + lane]);

    if (deg <= SCAP) {
        for (int j = 0; j < deg; j++) {
            int src = g_csr_src[r0 + j];
            const __nv_bfloat162* kk = (const __nv_bfloat162*)(g_kh + (size_t)src * DD);
#pragma unroll
            for (int h = 0; h < HH; h++) {
                float2 a = __bfloat1622float2(kk[h * 32 + lane]);
                float p = a.x * q2[h].x + a.y * q2[h].y;
#pragma unroll
                for (int off = 16; off > 0; off >>= 1)
                    p += __shfl_xor_sync(0xffffffffu, p, off);
                if (lane == 0) sbuf[w][j * HH + h] = m ? p : -1e4f;
            }
        }
        __syncwarp();
        if (lane < HH) {
            float mx = -3.4e38f;
            for (int j = 0; j < deg; j++) mx = fmaxf(mx, sbuf[w][j * HH + lane]);
            float s = 0.f;
            for (int j = 0; j < deg; j++) {
                float e = expf(sbuf[w][j * HH + lane] - mx);
                sbuf[w][j * HH + lane] = e;
                s += e;
            }
            float inv = 1.f / s;
            for (int j = 0; j < deg; j++)
                g_score[(size_t)(r0 + j) * HH + lane] = sbuf[w][j * HH + lane] * inv;
        }
    } else {
        // fallback (never hit for this input): scores via global, 3-pass softmax
        for (int j = 0; j < deg; j++) {
            int src = g_csr_src[r0 + j];
            const __nv_bfloat162* kk = (const __nv_bfloat162*)(g_kh + (size_t)src * DD);
#pragma unroll
            for (int h = 0; h < HH; h++) {
                float2 a = __bfloat1622float2(kk[h * 32 + lane]);
                float p = a.x * q2[h].x + a.y * q2[h].y;
#pragma unroll
                for (int off = 16; off > 0; off >>= 1)
                    p += __shfl_xor_sync(0xffffffffu, p, off);
                if (lane == 0) g_score[(size_t)(r0 + j) * HH + h] = m ? p : -1e4f;
            }
        }
        __syncwarp();
        if (lane < HH) {
            float mx = -3.4e38f;
            for (int j = 0; j < deg; j++)
                mx = fmaxf(mx, g_score[(size_t)(r0 + j) * HH + lane]);
            float s = 0.f;
            for (int j = 0; j < deg; j++)
                s += expf(g_score[(size_t)(r0 + j) * HH + lane] - mx);
            float inv = 1.f / s;
            for (int j = 0; j < deg; j++) {
                float e = expf(g_score[(size_t)(r0 + j) * HH + lane] - mx);
                g_score[(size_t)(r0 + j) * HH + lane] = e * inv;
            }
        }
    }
}

// -------- message passing: h_out = 0.9 * sum_e attn*h_in[src] + 0.1*v ----------
__global__ void mp_kernel(const __nv_bfloat16* __restrict__ hin,
                          __nv_bfloat16* __restrict__ hout,
                          float* __restrict__ houtf)
{
    int n = blockIdx.x;
    int t = threadIdx.x;   // 128 threads; bf162 slots t, t+128, t+256
    int r0 = g_rowptr[n], r1 = g_rowptr[n + 1];
    int h0 = t >> 5;           // 0..3
    float2 a0 = {0.f, 0.f}, a1 = {0.f, 0.f}, a2 = {0.f, 0.f};
    for (int i = r0; i < r1; i++) {
        const __nv_bfloat162* hs =
            (const __nv_bfloat162*)(hin + (size_t)g_csr_src[i] * DD);
        const float* at = g_score + (size_t)i * HH;
        float w0 = at[h0], w1 = at[h0 + 4], w2 = at[h0 + 8];
        float2 x0 = __bfloat1622float2(hs[t]);
        float2 x1 = __bfloat1622float2(hs[t + 128]);
        float2 x2 = __bfloat1622float2(hs[t + 256]);
        a0.x = fmaf(w0, x0.x, a0.x); a0.y = fmaf(w0, x0.y, a0.y);
        a1.x = fmaf(w1, x1.x, a1.x); a1.y = fmaf(w1, x1.y, a1.y);
        a2.x = fmaf(w2, x2.x, a2.x); a2.y = fmaf(w2, x2.y, a2.y);
    }
    const float2* vv = (const float2*)(g_v + (size_t)n * DD);
    float2 v0 = vv[t], v1 = vv[t + 128], v2 = vv[t + 256];
    float2 o0, o1, o2;
    o0.x = 0.9f * a0.x + 0.1f * v0.x;  o0.y = 0.9f * a0.y + 0.1f * v0.y;
    o1.x = 0.9f * a1.x + 0.1f * v1.x;  o1.y = 0.9f * a1.y + 0.1f * v1.y;
    o2.x = 0.9f * a2.x + 0.1f * v2.x;  o2.y = 0.9f * a2.y + 0.1f * v2.y;
    if (hout) {
        __nv_bfloat162* ob = (__nv_bfloat162*)(hout + (size_t)n * DD);
        ob[t]       = __floats2bfloat162_rn(o0.x, o0.y);
        ob[t + 128] = __floats2bfloat162_rn(o1.x, o1.y);
        ob[t + 256] = __floats2bfloat162_rn(o2.x, o2.y);
    }
    if (houtf) {
        float2* of = (float2*)(houtf + (size_t)n * DD);
        of[t] = o0; of[t + 128] = o1; of[t + 256] = o2;
    }
}

// ---------------- residual layernorm ----------------
__global__ void layernorm_kernel(const float* __restrict__ y,
                                 const float* __restrict__ gam,
                                 const float* __restrict__ bet,
                                 float* __restrict__ out)
{
    int row = blockIdx.x;
    int t = threadIdx.x;  // 256
    const float* yr = y + (size_t)row * DD;
    float v0 = yr[t], v1 = yr[t + 256], v2 = yr[t + 512];
    __shared__ float sh[256];
    sh[t] = v0 + v1 + v2;
    __syncthreads();
    for (int o = 128; o > 0; o >>= 1) { if (t < o) sh[t] += sh[t + o]; __syncthreads(); }
    float mu = sh[0] * (1.f / 768.f);
    __syncthreads();
    float d0 = v0 - mu, d1 = v1 - mu, d2 = v2 - mu;
    sh[t] = d0 * d0 + d1 * d1 + d2 * d2;
    __syncthreads();
    for (int o = 128; o > 0; o >>= 1) { if (t < o) sh[t] += sh[t + o]; __syncthreads(); }
    float inv = rsqrtf(sh[0] * (1.f / 768.f) + 1e-12f);
    float* orow = out + (size_t)row * DD;
    orow[t]       = d0 * inv * gam[t]       + bet[t];
    orow[t + 256] = d1 * inv * gam[t + 256] + bet[t + 256];
    orow[t + 512] = d2 * inv * gam[t + 512] + bet[t + 512];
}

// ---------------- launch ----------------
extern "C" void kernel_launch(void* const* d_in, const int* in_sizes, int n_in,
                              void* d_out, int out_size)
{
    const float* x    = (const float*)d_in[0];
    const float* mask = (const float*)d_in[1];
    const int*   esrc = (const int*)d_in[2];
    const int*   edst = (const int*)d_in[3];
    const float* Wq = (const float*)d_in[4];  const float* bq = (const float*)d_in[5];
    const float* Wk = (const float*)d_in[6];  const float* bk = (const float*)d_in[7];
    const float* Wv = (const float*)d_in[8];  const float* bv = (const float*)d_in[9];
    const float* Wo = (const float*)d_in[10]; const float* bo = (const float*)d_in[11];
    const float* lg = (const float*)d_in[12]; const float* lb = (const float*)d_in[13];
    float* out = (float*)d_out;

    float *vp, *yp;
    __nv_bfloat16 *xhp, *whp, *qhp, *khp, *vhp, *hb0p, *hb1p;
    int* cntp;
    cudaGetSymbolAddress((void**)&vp,   g_v);
    cudaGetSymbolAddress((void**)&yp,   g_y);
    cudaGetSymbolAddress((void**)&xhp,  g_xh);
    cudaGetSymbolAddress((void**)&whp,  g_wh);
    cudaGetSymbolAddress((void**)&qhp,  g_qh);
    cudaGetSymbolAddress((void**)&khp,  g_kh);
    cudaGetSymbolAddress((void**)&vhp,  g_vh);
    cudaGetSymbolAddress((void**)&hb0p, g_hb0);
    cudaGetSymbolAddress((void**)&hb1p, g_hb1);
    cudaGetSymbolAddress((void**)&cntp, g_cnt);

    __nv_bfloat16* wqh = whp;
    __nv_bfloat16* wkh = whp + (size_t)DD * DD;
    __nv_bfloat16* wvh = whp + 2 * (size_t)DD * DD;
    __nv_bfloat16* woh = whp + 3 * (size_t)DD * DD;

    cudaFuncSetAttribute(gemm_bf16, cudaFuncAttributeMaxDynamicSharedMemorySize, GEMM_SMEM);

    // ---- fp32 -> bf16 conversions (x and the four weights) ----
    {
        int n4 = NN * DD / 4;
        cvt_bf16_kernel<<<(n4 + 255) / 256, 256>>>((const float4*)x, (__nv_bfloat162*)xhp, n4);
        int w4 = DD * DD / 4;
        cvt_bf16_kernel<<<(w4 + 255) / 256, 256>>>((const float4*)Wq, (__nv_bfloat162*)wqh, w4);
        cvt_bf16_kernel<<<(w4 + 255) / 256, 256>>>((const float4*)Wk, (__nv_bfloat162*)wkh, w4);
        cvt_bf16_kernel<<<(w4 + 255) / 256, 256>>>((const float4*)Wv, (__nv_bfloat162*)wvh, w4);
        cvt_bf16_kernel<<<(w4 + 255) / 256, 256>>>((const float4*)Wo, (__nv_bfloat162*)woh, w4);
    }

    dim3 ggrid(DD / 128, NN / 128);   // (6, 64)

    // q,k -> bf16 only; v -> fp32 (mix) + bf16 (first gather)
    gemm_bf16<<<ggrid, 256, GEMM_SMEM>>>(xhp, wqh, bq, nullptr, nullptr, qhp, 0.125f);
    gemm_bf16<<<ggrid, 256, GEMM_SMEM>>>(xhp, wkh, bk, nullptr, nullptr, khp, 1.0f);
    gemm_bf16<<<ggrid, 256, GEMM_SMEM>>>(xhp, wvh, bv, nullptr, vp, vhp, 1.0f);

    // CSR build (deterministic: per-row sort by edge id)
    cudaMemsetAsync(cntp, 0, NN * sizeof(int), 0);
    hist_kernel<<<(EE + 255) / 256, 256>>>(edst);
    scan_kernel<<<1, 1024>>>();
    scatter_kernel<<<(EE + 255) / 256, 256>>>(edst);
    sort_rows_kernel<<<NN, 32>>>(esrc);

    // fused edge scores + per-dst softmax (warp per node)
    score_softmax_kernel<<<NN / 8, 256>>>(mask);

    // 5 message-passing steps (bf16 ping-pong; last emits bf16 h for Wo GEMM)
    mp_kernel<<<NN, 128>>>(vhp,  hb0p, nullptr);
    mp_kernel<<<NN, 128>>>(hb0p, hb1p, nullptr);
    mp_kernel<<<NN, 128>>>(hb1p, hb0p, nullptr);
    mp_kernel<<<NN, 128>>>(hb0p, hb1p, nullptr);
    mp_kernel<<<NN, 128>>>(hb1p, hb0p, nullptr);

    // output projection + residual (A = bf16 h), then layernorm
    gemm_bf16<<<ggrid, 256, GEMM_SMEM>>>(hb0p, woh, bo, x, yp, nullptr, 1.0f);
    layernorm_kernel<<<NN, 256>>>(yp, lg, lb, out);
}

// round 10
// speedup vs baseline: 3.3398x; 1.0716x over previous
#include <cuda_runtime.h>
#include <cuda_bf16.h>
#include <cstdint>
#include <math.h>

// Problem constants
#define NN   8192          // B*S nodes
#define DD   768           // hidden dim
#define EE   131072        // edges
#define HH   12            // heads
#define HDD  64            // head dim

// ---------------- scratch (static device globals; no allocation) ----------------
__device__ float g_v[NN * DD];             // v fp32 (mix term)
__device__ float g_y[NN * DD];
__device__ __nv_bfloat16 g_xh[NN * DD];    // hidden_states bf16 (GEMM A input)
__device__ __nv_bfloat16 g_wh[4 * DD * DD];// Wq,Wk,Wv,Wo bf16 (contiguous!)
__device__ __nv_bfloat16 g_qh[NN * DD];    // q (bf16, pre-scaled)
__device__ __nv_bfloat16 g_kh[NN * DD];    // k (bf16)
__device__ __nv_bfloat16 g_vh[NN * DD];    // v (bf16, mp step-1 gather input)
__device__ __nv_bfloat16 g_hb0[NN * DD];   // h ping (bf16)
__device__ __nv_bfloat16 g_hb1[NN * DD];   // h pong (bf16)
__device__ float g_score[EE * HH];         // attn weights
__device__ int   g_cnt[NN];
__device__ int   g_rowptr[NN + 1];
__device__ int   g_cursor[NN];
__device__ int   g_csr_eid[EE];
__device__ int   g_csr_src[EE];

__device__ __forceinline__ uint32_t smem_cast(const void* p) {
    return (uint32_t)__cvta_generic_to_shared(p);
}

// ------------- fused fp32 -> bf16 conversion (x + all 4 weights, one launch) ----
__global__ void cvt_all_kernel(const float4* __restrict__ x,
                               const float4* __restrict__ wq, const float4* __restrict__ wk,
                               const float4* __restrict__ wv, const float4* __restrict__ wo,
                               __nv_bfloat162* __restrict__ xh, __nv_bfloat162* __restrict__ wh)
{
    const int NX = NN * DD / 4;
    const int NW = DD * DD / 4;
    int i = blockIdx.x * blockDim.x + threadIdx.x;
    if (i >= NX + 4 * NW) return;
    float4 v;
    __nv_bfloat162* d;
    if (i < NX) {
        v = x[i];
        d = xh + 2 * (size_t)i;
    } else {
        int j = i - NX;
        int w = j / NW, o = j - w * NW;
        const float4* s = (w == 0) ? wq : (w == 1) ? wk : (w == 2) ? wv : wo;
        v = s[o];
        d = wh + 2 * (size_t)j;
    }
    d[0] = __floats2bfloat162_rn(v.x, v.y);
    d[1] = __floats2bfloat162_rn(v.z, v.w);
}

// ================= bf16 warp-MMA GEMM (m16n8k16, ldmatrix A, 3-stage) =====
#define BKK    32                        // k-step (bf16 elems)
#define LDH    40                        // 32 + 8 pad bf16 per row
#define STG_H  (128 * LDH * 2)           // bf16 elems per stage (A + B)
#define GST    3
#define GEMM_SMEM (GST * STG_H * 2)      // bytes = 61440
#define NKT    (DD / BKK)                // 24

// ---- shared mainloop (macro keeps both kernels identical in the hot path) ----
#define GEMM_MAINLOOP(Ab, Wb)                                                        \
    float acc[4][4][4];                                                              \
    _Pragma("unroll")                                                                \
    for (int mt = 0; mt < 4; mt++)                                                   \
        _Pragma("unroll")                                                            \
        for (int nt = 0; nt < 4; nt++)                                               \
            _Pragma("unroll")                                                        \
            for (int c = 0; c < 4; c++) acc[mt][nt][c] = 0.f;                        \
    auto load_stage = [&](int kt, int stg) {                                         \
        __nv_bfloat16* Abase = smh + stg * STG_H;                                    \
        __nv_bfloat16* Bbase = Abase + 128 * LDH;                                    \
        _Pragma("unroll")                                                            \
        for (int i = 0; i < 2; i++) {                                                \
            int idx = tid + i * 256;                                                 \
            int row = idx >> 2;                                                      \
            int c16 = idx & 3;                                                       \
            const __nv_bfloat16* ga = Ab + (size_t)row * DD + kt * BKK + c16 * 8;    \
            const __nv_bfloat16* gb = Wb + (size_t)row * DD + kt * BKK + c16 * 8;    \
            uint32_t da = smem_cast(Abase + row * LDH + c16 * 8);                    \
            uint32_t db = smem_cast(Bbase + row * LDH + c16 * 8);                    \
            asm volatile("cp.async.cg.shared.global [%0], [%1], 16;" :: "r"(da), "l"(ga)); \
            asm volatile("cp.async.cg.shared.global [%0], [%1], 16;" :: "r"(db), "l"(gb)); \
        }                                                                            \
        asm volatile("cp.async.commit_group;");                                      \
    };                                                                               \
    load_stage(0, 0);                                                                \
    load_stage(1, 1);                                                                \
    const int lm_row = lane & 15;                                                    \
    const int lm_kh  = (lane >> 4) * 8;                                              \
    for (int kt = 0; kt < NKT; kt++) {                                               \
        if (kt + 1 < NKT) { asm volatile("cp.async.wait_group 1;"); }                \
        else              { asm volatile("cp.async.wait_group 0;"); }                \
        __syncthreads();                                                             \
        if (kt + 2 < NKT) load_stage(kt + 2, (kt + 2) % GST);                        \
        const __nv_bfloat16* Abase = smh + (kt % GST) * STG_H;                       \
        const __nv_bfloat16* Bbase = Abase + 128 * LDH;                              \
        const __nv_bfloat16* Aw = Abase + (wm * 64) * LDH;                           \
        const __nv_bfloat16* Bw = Bbase + (wn * 32) * LDH;                           \
        _Pragma("unroll")                                                            \
        for (int ks = 0; ks < 2; ks++) {                                             \
            const int k0 = ks * 16;                                                  \
            uint32_t bfr[4][2];                                                      \
            _Pragma("unroll")                                                        \
            for (int nt = 0; nt < 4; nt++) {                                         \
                const __nv_bfloat16* bp = Bw + (nt * 8 + gq) * LDH + k0;             \
                bfr[nt][0] = *(const uint32_t*)(bp + 2 * tg);                        \
                bfr[nt][1] = *(const uint32_t*)(bp + 2 * tg + 8);                    \
            }                                                                        \
            _Pragma("unroll")                                                        \
            for (int mt = 0; mt < 4; mt++) {                                         \
                uint32_t a0, a1, a2, a3;                                             \
                uint32_t addr = smem_cast(Aw + (mt * 16 + lm_row) * LDH + k0 + lm_kh); \
                asm volatile(                                                        \
                    "ldmatrix.sync.aligned.m8n8.x4.shared.b16 {%0,%1,%2,%3}, [%4];"  \
                    : "=r"(a0), "=r"(a1), "=r"(a2), "=r"(a3) : "r"(addr));           \
                _Pragma("unroll")                                                    \
                for (int nt = 0; nt < 4; nt++) {                                     \
                    asm volatile(                                                    \
                        "mma.sync.aligned.m16n8k16.row.col.f32.bf16.bf16.f32 "       \
                        "{%0,%1,%2,%3}, {%4,%5,%6,%7}, {%8,%9}, {%0,%1,%2,%3};"      \
                        : "+f"(acc[mt][nt][0]), "+f"(acc[mt][nt][1]),                \
                          "+f"(acc[mt][nt][2]), "+f"(acc[mt][nt][3])                 \
                        : "r"(a0), "r"(a1), "r"(a2), "r"(a3),                        \
                          "r"(bfr[nt][0]), "r"(bfr[nt][1]));                         \
                }                                                                    \
            }                                                                        \
        }                                                                            \
    }

// ---- merged QKV GEMM: N = 2304 (sectors: q | k | v) ----
__global__ __launch_bounds__(256, 2)
void gemm_qkv(const __nv_bfloat16* __restrict__ A, const __nv_bfloat16* __restrict__ Wall,
              const float* __restrict__ bq, const float* __restrict__ bk,
              const float* __restrict__ bv,
              __nv_bfloat16* __restrict__ qh, __nv_bfloat16* __restrict__ kh,
              float* __restrict__ v, __nv_bfloat16* __restrict__ vh)
{
    extern __shared__ __nv_bfloat16 smh[];
    const int tid  = threadIdx.x;
    const int wid  = tid >> 5;
    const int lane = tid & 31;
    const int gq   = lane >> 2;
    const int tg   = lane & 3;
    const int wm   = wid >> 2;
    const int wn   = wid & 3;
    const int bm   = blockIdx.y * 128;
    const int bn   = blockIdx.x * 128;        // 0..2303
    const int sector = blockIdx.x / 6;        // 0=q 1=k 2=v
    const int cbase  = bn - sector * DD;      // column within sector

    const __nv_bfloat16* Ab = A + (size_t)bm * DD;
    const __nv_bfloat16* Wb = Wall + (size_t)bn * DD;

    GEMM_MAINLOOP(Ab, Wb)

    const float* bias = (sector == 0) ? bq : (sector == 1) ? bk : bv;
    const float alpha = (sector == 0) ? 0.125f : 1.0f;

#pragma unroll
    for (int mt = 0; mt < 4; mt++) {
        int r0 = bm + wm * 64 + mt * 16 + gq;
        int r1 = r0 + 8;
#pragma unroll
        for (int nt = 0; nt < 4; nt++) {
            int cl = cbase + wn * 32 + nt * 8 + tg * 2;
            float b0 = bias[cl], b1 = bias[cl + 1];
            float2 o0, o1;
            o0.x = (acc[mt][nt][0] + b0) * alpha;
            o0.y = (acc[mt][nt][1] + b1) * alpha;
            o1.x = (acc[mt][nt][2] + b0) * alpha;
            o1.y = (acc[mt][nt][3] + b1) * alpha;
            __nv_bfloat162 h0 = __floats2bfloat162_rn(o0.x, o0.y);
            __nv_bfloat162 h1 = __floats2bfloat162_rn(o1.x, o1.y);
            if (sector == 0) {
                *(__nv_bfloat162*)(qh + (size_t)r0 * DD + cl) = h0;
                *(__nv_bfloat162*)(qh + (size_t)r1 * DD + cl) = h1;
            } else if (sector == 1) {
                *(__nv_bfloat162*)(kh + (size_t)r0 * DD + cl) = h0;
                *(__nv_bfloat162*)(kh + (size_t)r1 * DD + cl) = h1;
            } else {
                *(float2*)(v + (size_t)r0 * DD + cl) = o0;
                *(float2*)(v + (size_t)r1 * DD + cl) = o1;
                *(__nv_bfloat162*)(vh + (size_t)r0 * DD + cl) = h0;
                *(__nv_bfloat162*)(vh + (size_t)r1 * DD + cl) = h1;
            }
        }
    }
}

// ---- Wo GEMM: C = A @ Wo^T + bias + resid (fp32 out) ----
__global__ __launch_bounds__(256, 2)
void gemm_out(const __nv_bfloat16* __restrict__ A, const __nv_bfloat16* __restrict__ W,
              const float* __restrict__ bias, const float* __restrict__ resid,
              float* __restrict__ C)
{
    extern __shared__ __nv_bfloat16 smh[];
    const int tid  = threadIdx.x;
    const int wid  = tid >> 5;
    const int lane = tid & 31;
    const int gq   = lane >> 2;
    const int tg   = lane & 3;
    const int wm   = wid >> 2;
    const int wn   = wid & 3;
    const int bm   = blockIdx.y * 128;
    const int bn   = blockIdx.x * 128;

    const __nv_bfloat16* Ab = A + (size_t)bm * DD;
    const __nv_bfloat16* Wb = W + (size_t)bn * DD;

    GEMM_MAINLOOP(Ab, Wb)

#pragma unroll
    for (int mt = 0; mt < 4; mt++) {
        int r0 = bm + wm * 64 + mt * 16 + gq;
        int r1 = r0 + 8;
#pragma unroll
        for (int nt = 0; nt < 4; nt++) {
            int col = bn + wn * 32 + nt * 8 + tg * 2;
            float b0 = bias[col], b1 = bias[col + 1];
            float2 o0, o1;
            o0.x = acc[mt][nt][0] + b0 + resid[(size_t)r0 * DD + col];
            o0.y = acc[mt][nt][1] + b1 + resid[(size_t)r0 * DD + col + 1];
            o1.x = acc[mt][nt][2] + b0 + resid[(size_t)r1 * DD + col];
            o1.y = acc[mt][nt][3] + b1 + resid[(size_t)r1 * DD + col + 1];
            *(float2*)(C + (size_t)r0 * DD + col) = o0;
            *(float2*)(C + (size_t)r1 * DD + col) = o1;
        }
    }
}

// ---------------- CSR build ----------------
__global__ void hist_kernel(const int* __restrict__ dst)
{
    int e = blockIdx.x * blockDim.x + threadIdx.x;
    if (e < EE) atomicAdd(&g_cnt[dst[e]], 1);
}

__global__ void scan_kernel()
{
    __shared__ int sh[1024];
    int t = threadIdx.x;
    int base = t * 8;
    int loc[8];
    int s = 0;
#pragma unroll
    for (int j = 0; j < 8; j++) { loc[j] = s; s += g_cnt[base + j]; }
    sh[t] = s;
    __syncthreads();
    for (int off = 1; off < 1024; off <<= 1) {
        int v = (t >= off) ? sh[t - off] : 0;
        __syncthreads();
        sh[t] += v;
        __syncthreads();
    }
    int excl = (t > 0) ? sh[t - 1] : 0;
#pragma unroll
    for (int j = 0; j < 8; j++) {
        g_rowptr[base + j] = excl + loc[j];
        g_cursor[base + j] = excl + loc[j];
    }
    if (t == 1023) g_rowptr[NN] = excl + s;
}

__global__ void scatter_kernel(const int* __restrict__ dst)
{
    int e = blockIdx.x * blockDim.x + threadIdx.x;
    if (e < EE) {
        int p = atomicAdd(&g_cursor[dst[e]], 1);
        g_csr_eid[p] = e;
    }
}

// per-row sort by original edge id -> deterministic fp reduction order
__global__ void sort_rows_kernel(const int* __restrict__ edge_src)
{
    int n = blockIdx.x;
    int r0 = g_rowptr[n], r1 = g_rowptr[n + 1];
    int deg = r1 - r0;
    int lane = threadIdx.x;
    __shared__ int sh[2048];
    if (deg <= 2048) {
        for (int i = lane; i < deg; i += 32) sh[i] = g_csr_eid[r0 + i];
        __syncwarp();
        for (int p = 0; p < deg; p++) {
            for (int i = (p & 1) + 2 * lane; i + 1 < deg; i += 64) {
                int a = sh[i], b = sh[i + 1];
                if (a > b) { sh[i] = b; sh[i + 1] = a; }
            }
            __syncwarp();
        }
        for (int i = lane; i < deg; i += 32) {
            int e = sh[i];
            g_csr_eid[r0 + i] = e;
            g_csr_src[r0 + i] = edge_src[e];
        }
    } else {
        for (int i = lane; i < deg; i += 32) {
            int e = g_csr_eid[r0 + i];
            g_csr_src[r0 + i] = edge_src[e];
        }
    }
}

// ====== fused edge-score + softmax: warp per dst node, q in registers ======
#define SCAP 128
__global__ __launch_bounds__(256)
void score_softmax_kernel(const float* __restrict__ mask)
{
    __shared__ float sbuf[8][SCAP * HH];   // 48 KB
    int w = threadIdx.x >> 5;
    int lane = threadIdx.x & 31;
    int node = blockIdx.x * 8 + w;
    int r0 = g_rowptr[node], r1 = g_rowptr[node + 1];
    int deg = r1 - r0;
    bool m = (mask[node] >= 0.f);

    const __nv_bfloat162* qq = (const __nv_bfloat162*)(g_qh + (size_t)node * DD);
    float2 q2[HH];
#pragma unroll
    for (int h = 0; h < HH; h++) q2[h] = __bfloat1622float2(qq[h * 32 + lane]);

    if (deg <= SCAP) {
        for (int j = 0; j < deg; j++) {
            int src = g_csr_src[r0 + j];
            const __nv_bfloat162* kk = (const __nv_bfloat162*)(g_kh + (size_t)src * DD);
#pragma unroll
            for (int h = 0; h < HH; h++) {
                float2 a = __bfloat1622float2(kk[h * 32 + lane]);
                float p = a.x * q2[h].x + a.y * q2[h].y;
#pragma unroll
                for (int off = 16; off > 0; off >>= 1)
                    p += __shfl_xor_sync(0xffffffffu, p, off);
                if (lane == 0) sbuf[w][j * HH + h] = m ? p : -1e4f;
            }
        }
        __syncwarp();
        if (lane < HH) {
            float mx = -3.4e38f;
            for (int j = 0; j < deg; j++) mx = fmaxf(mx, sbuf[w][j * HH + lane]);
            float s = 0.f;
            for (int j = 0; j < deg; j++) {
                float e = expf(sbuf[w][j * HH + lane] - mx);
                sbuf[w][j * HH + lane] = e;
                s += e;
            }
            float inv = 1.f / s;
            for (int j = 0; j < deg; j++)
                g_score[(size_t)(r0 + j) * HH + lane] = sbuf[w][j * HH + lane] * inv;
        }
    } else {
        // fallback (never hit for this input)
        for (int j = 0; j < deg; j++) {
            int src = g_csr_src[r0 + j];
            const __nv_bfloat162* kk = (const __nv_bfloat162*)(g_kh + (size_t)src * DD);
#pragma unroll
            for (int h = 0; h < HH; h++) {
                float2 a = __bfloat1622float2(kk[h * 32 + lane]);
                float p = a.x * q2[h].x + a.y * q2[h].y;
#pragma unroll
                for (int off = 16; off > 0; off >>= 1)
                    p += __shfl_xor_sync(0xffffffffu, p, off);
                if (lane == 0) g_score[(size_t)(r0 + j) * HH + h] = m ? p : -1e4f;
            }
        }
        __syncwarp();
        if (lane < HH) {
            float mx = -3.4e38f;
            for (int j = 0; j < deg; j++)
                mx = fmaxf(mx, g_score[(size_t)(r0 + j) * HH + lane]);
            float s = 0.f;
            for (int j = 0; j < deg; j++)
                s += expf(g_score[(size_t)(r0 + j) * HH + lane] - mx);
            float inv = 1.f / s;
            for (int j = 0; j < deg; j++) {
                float e = expf(g_score[(size_t)(r0 + j) * HH + lane] - mx);
                g_score[(size_t)(r0 + j) * HH + lane] = e * inv;
            }
        }
    }
}

// -------- message passing: h_out = 0.9 * sum_e attn*h_in[src] + 0.1*v ----------
__global__ void mp_kernel(const __nv_bfloat16* __restrict__ hin,
                          __nv_bfloat16* __restrict__ hout,
                          float* __restrict__ houtf)
{
    int n = blockIdx.x;
    int t = threadIdx.x;   // 128 threads; bf162 slots t, t+128, t+256
    int r0 = g_rowptr[n], r1 = g_rowptr[n + 1];
    int h0 = t >> 5;
    float2 a0 = {0.f, 0.f}, a1 = {0.f, 0.f}, a2 = {0.f, 0.f};
    for (int i = r0; i < r1; i++) {
        const __nv_bfloat162* hs =
            (const __nv_bfloat162*)(hin + (size_t)g_csr_src[i] * DD);
        const float* at = g_score + (size_t)i * HH;
        float w0 = at[h0], w1 = at[h0 + 4], w2 = at[h0 + 8];
        float2 x0 = __bfloat1622float2(hs[t]);
        float2 x1 = __bfloat1622float2(hs[t + 128]);
        float2 x2 = __bfloat1622float2(hs[t + 256]);
        a0.x = fmaf(w0, x0.x, a0.x); a0.y = fmaf(w0, x0.y, a0.y);
        a1.x = fmaf(w1, x1.x, a1.x); a1.y = fmaf(w1, x1.y, a1.y);
        a2.x = fmaf(w2, x2.x, a2.x); a2.y = fmaf(w2, x2.y, a2.y);
    }
    const float2* vv = (const float2*)(g_v + (size_t)n * DD);
    float2 v0 = vv[t], v1 = vv[t + 128], v2 = vv[t + 256];
    float2 o0, o1, o2;
    o0.x = 0.9f * a0.x + 0.1f * v0.x;  o0.y = 0.9f * a0.y + 0.1f * v0.y;
    o1.x = 0.9f * a1.x + 0.1f * v1.x;  o1.y = 0.9f * a1.y + 0.1f * v1.y;
    o2.x = 0.9f * a2.x + 0.1f * v2.x;  o2.y = 0.9f * a2.y + 0.1f * v2.y;
    if (hout) {
        __nv_bfloat162* ob = (__nv_bfloat162*)(hout + (size_t)n * DD);
        ob[t]       = __floats2bfloat162_rn(o0.x, o0.y);
        ob[t + 128] = __floats2bfloat162_rn(o1.x, o1.y);
        ob[t + 256] = __floats2bfloat162_rn(o2.x, o2.y);
    }
    if (houtf) {
        float2* of = (float2*)(houtf + (size_t)n * DD);
        of[t] = o0; of[t + 128] = o1; of[t + 256] = o2;
    }
}

// ---------------- residual layernorm ----------------
__global__ void layernorm_kernel(const float* __restrict__ y,
                                 const float* __restrict__ gam,
                                 const float* __restrict__ bet,
                                 float* __restrict__ out)
{
    int row = blockIdx.x;
    int t = threadIdx.x;  // 256
    const float* yr = y + (size_t)row * DD;
    float v0 = yr[t], v1 = yr[t + 256], v2 = yr[t + 512];
    __shared__ float sh[256];
    sh[t] = v0 + v1 + v2;
    __syncthreads();
    for (int o = 128; o > 0; o >>= 1) { if (t < o) sh[t] += sh[t + o]; __syncthreads(); }
    float mu = sh[0] * (1.f / 768.f);
    __syncthreads();
    float d0 = v0 - mu, d1 = v1 - mu, d2 = v2 - mu;
    sh[t] = d0 * d0 + d1 * d1 + d2 * d2;
    __syncthreads();
    for (int o = 128; o > 0; o >>= 1) { if (t < o) sh[t] += sh[t + o]; __syncthreads(); }
    float inv = rsqrtf(sh[0] * (1.f / 768.f) + 1e-12f);
    float* orow = out + (size_t)row * DD;
    orow[t]       = d0 * inv * gam[t]       + bet[t];
    orow[t + 256] = d1 * inv * gam[t + 256] + bet[t + 256];
    orow[t + 512] = d2 * inv * gam[t + 512] + bet[t + 512];
}

// ---------------- launch ----------------
extern "C" void kernel_launch(void* const* d_in, const int* in_sizes, int n_in,
                              void* d_out, int out_size)
{
    const float* x    = (const float*)d_in[0];
    const float* mask = (const float*)d_in[1];
    const int*   esrc = (const int*)d_in[2];
    const int*   edst = (const int*)d_in[3];
    const float* Wq = (const float*)d_in[4];  const float* bq = (const float*)d_in[5];
    const float* Wk = (const float*)d_in[6];  const float* bk = (const float*)d_in[7];
    const float* Wv = (const float*)d_in[8];  const float* bv = (const float*)d_in[9];
    const float* Wo = (const float*)d_in[10]; const float* bo = (const float*)d_in[11];
    const float* lg = (const float*)d_in[12]; const float* lb = (const float*)d_in[13];
    float* out = (float*)d_out;

    float *vp, *yp;
    __nv_bfloat16 *xhp, *whp, *qhp, *khp, *vhp, *hb0p, *hb1p;
    int* cntp;
    cudaGetSymbolAddress((void**)&vp,   g_v);
    cudaGetSymbolAddress((void**)&yp,   g_y);
    cudaGetSymbolAddress((void**)&xhp,  g_xh);
    cudaGetSymbolAddress((void**)&whp,  g_wh);
    cudaGetSymbolAddress((void**)&qhp,  g_qh);
    cudaGetSymbolAddress((void**)&khp,  g_kh);
    cudaGetSymbolAddress((void**)&vhp,  g_vh);
    cudaGetSymbolAddress((void**)&hb0p, g_hb0);
    cudaGetSymbolAddress((void**)&hb1p, g_hb1);
    cudaGetSymbolAddress((void**)&cntp, g_cnt);

    __nv_bfloat16* woh = whp + 3 * (size_t)DD * DD;

    cudaFuncSetAttribute(gemm_qkv, cudaFuncAttributeMaxDynamicSharedMemorySize, GEMM_SMEM);
    cudaFuncSetAttribute(gemm_out, cudaFuncAttributeMaxDynamicSharedMemorySize, GEMM_SMEM);

    // ---- fused fp32 -> bf16 conversion (x + 4 weights, one launch) ----
    {
        int total = NN * DD / 4 + 4 * (DD * DD / 4);
        cvt_all_kernel<<<(total + 255) / 256, 256>>>(
            (const float4*)x, (const float4*)Wq, (const float4*)Wk,
            (const float4*)Wv, (const float4*)Wo,
            (__nv_bfloat162*)xhp, (__nv_bfloat162*)whp);
    }

    // ---- merged q/k/v projection: one GEMM, N = 2304 ----
    {
        dim3 qkvgrid(3 * DD / 128, NN / 128);   // (18, 64)
        gemm_qkv<<<qkvgrid, 256, GEMM_SMEM>>>(xhp, whp, bq, bk, bv, qhp, khp, vp, vhp);
    }

    // CSR build (deterministic: per-row sort by edge id)
    cudaMemsetAsync(cntp, 0, NN * sizeof(int), 0);
    hist_kernel<<<(EE + 255) / 256, 256>>>(edst);
    scan_kernel<<<1, 1024>>>();
    scatter_kernel<<<(EE + 255) / 256, 256>>>(edst);
    sort_rows_kernel<<<NN, 32>>>(esrc);

    // fused edge scores + per-dst softmax (warp per node)
    score_softmax_kernel<<<NN / 8, 256>>>(mask);

    // 5 message-passing steps (bf16 ping-pong)
    mp_kernel<<<NN, 128>>>(vhp,  hb0p, nullptr);
    mp_kernel<<<NN, 128>>>(hb0p, hb1p, nullptr);
    mp_kernel<<<NN, 128>>>(hb1p, hb0p, nullptr);
    mp_kernel<<<NN, 128>>>(hb0p, hb1p, nullptr);
    mp_kernel<<<NN, 128>>>(hb1p, hb0p, nullptr);

    // output projection + residual, then layernorm
    {
        dim3 ogrid(DD / 128, NN / 128);         // (6, 64)
        gemm_out<<<ogrid, 256, GEMM_SMEM>>>(hb0p, woh, bo, x, yp);
    }
    layernorm_kernel<<<NN, 256>>>(yp, lg, lb, out);
}

// round 11
// speedup vs baseline: 3.4431x; 1.0310x over previous
#include <cuda_runtime.h>
#include <cuda_bf16.h>
#include <cstdint>
#include <math.h>

// Problem constants
#define NN   8192          // B*S nodes
#define DD   768           // hidden dim
#define EE   131072        // edges
#define HH   12            // heads
#define HDD  64            // head dim

// ---------------- scratch (static device globals; no allocation) ----------------
__device__ float g_y[NN * DD];
__device__ __nv_bfloat16 g_xh[NN * DD];    // hidden_states bf16 (GEMM A input)
__device__ __nv_bfloat16 g_wh[4 * DD * DD];// Wq,Wk,Wv,Wo bf16 (contiguous)
__device__ __nv_bfloat16 g_qh[NN * DD];    // q (bf16, pre-scaled)
__device__ __nv_bfloat16 g_kh[NN * DD];    // k (bf16)
__device__ __nv_bfloat16 g_vh[NN * DD];    // v (bf16: gather + mix term)
__device__ __nv_bfloat16 g_hb0[NN * DD];   // h ping (bf16)
__device__ __nv_bfloat16 g_hb1[NN * DD];   // h pong (bf16)
__device__ float g_score[EE * HH];         // attn weights
__device__ int   g_cnt[NN];
__device__ int   g_rowptr[NN + 1];
__device__ int   g_cursor[NN];
__device__ int   g_csr_eid[EE];
__device__ int   g_csr_src[EE];

__device__ __forceinline__ uint32_t smem_cast(const void* p) {
    return (uint32_t)__cvta_generic_to_shared(p);
}

// ------------- fused fp32 -> bf16 conversion (x + all 4 weights, one launch) ----
__global__ void cvt_all_kernel(const float4* __restrict__ x,
                               const float4* __restrict__ wq, const float4* __restrict__ wk,
                               const float4* __restrict__ wv, const float4* __restrict__ wo,
                               __nv_bfloat162* __restrict__ xh, __nv_bfloat162* __restrict__ wh)
{
    const int NX = NN * DD / 4;
    const int NW = DD * DD / 4;
    int i = blockIdx.x * blockDim.x + threadIdx.x;
    if (i >= NX + 4 * NW) return;
    float4 v;
    __nv_bfloat162* d;
    if (i < NX) {
        v = x[i];
        d = xh + 2 * (size_t)i;
    } else {
        int j = i - NX;
        int w = j / NW, o = j - w * NW;
        const float4* s = (w == 0) ? wq : (w == 1) ? wk : (w == 2) ? wv : wo;
        v = s[o];
        d = wh + 2 * (size_t)j;
    }
    d[0] = __floats2bfloat162_rn(v.x, v.y);
    d[1] = __floats2bfloat162_rn(v.z, v.w);
}

// ================= bf16 warp-MMA GEMM (m16n8k16, ldmatrix A, 3-stage) =====
#define BKK    32                        // k-step (bf16 elems)
#define LDH    40                        // 32 + 8 pad bf16 per row
#define STG_H  (128 * LDH * 2)           // bf16 elems per stage (A + B)
#define GST    3
#define GEMM_SMEM (GST * STG_H * 2)      // bytes = 61440
#define NKT    (DD / BKK)                // 24

#define GEMM_MAINLOOP(Ab, Wb)                                                        \
    float acc[4][4][4];                                                              \
    _Pragma("unroll")                                                                \
    for (int mt = 0; mt < 4; mt++)                                                   \
        _Pragma("unroll")                                                            \
        for (int nt = 0; nt < 4; nt++)                                               \
            _Pragma("unroll")                                                        \
            for (int c = 0; c < 4; c++) acc[mt][nt][c] = 0.f;                        \
    auto load_stage = [&](int kt, int stg) {                                         \
        __nv_bfloat16* Abase = smh + stg * STG_H;                                    \
        __nv_bfloat16* Bbase = Abase + 128 * LDH;                                    \
        _Pragma("unroll")                                                            \
        for (int i = 0; i < 2; i++) {                                                \
            int idx = tid + i * 256;                                                 \
            int row = idx >> 2;                                                      \
            int c16 = idx & 3;                                                       \
            const __nv_bfloat16* ga = Ab + (size_t)row * DD + kt * BKK + c16 * 8;    \
            const __nv_bfloat16* gb = Wb + (size_t)row * DD + kt * BKK + c16 * 8;    \
            uint32_t da = smem_cast(Abase + row * LDH + c16 * 8);                    \
            uint32_t db = smem_cast(Bbase + row * LDH + c16 * 8);                    \
            asm volatile("cp.async.cg.shared.global [%0], [%1], 16;" :: "r"(da), "l"(ga)); \
            asm volatile("cp.async.cg.shared.global [%0], [%1], 16;" :: "r"(db), "l"(gb)); \
        }                                                                            \
        asm volatile("cp.async.commit_group;");                                      \
    };                                                                               \
    load_stage(0, 0);                                                                \
    load_stage(1, 1);                                                                \
    const int lm_row = lane & 15;                                                    \
    const int lm_kh  = (lane >> 4) * 8;                                              \
    for (int kt = 0; kt < NKT; kt++) {                                               \
        if (kt + 1 < NKT) { asm volatile("cp.async.wait_group 1;"); }                \
        else              { asm volatile("cp.async.wait_group 0;"); }                \
        __syncthreads();                                                             \
        if (kt + 2 < NKT) load_stage(kt + 2, (kt + 2) % GST);                        \
        const __nv_bfloat16* Abase = smh + (kt % GST) * STG_H;                       \
        const __nv_bfloat16* Bbase = Abase + 128 * LDH;                              \
        const __nv_bfloat16* Aw = Abase + (wm * 64) * LDH;                           \
        const __nv_bfloat16* Bw = Bbase + (wn * 32) * LDH;                           \
        _Pragma("unroll")                                                            \
        for (int ks = 0; ks < 2; ks++) {                                             \
            const int k0 = ks * 16;                                                  \
            uint32_t bfr[4][2];                                                      \
            _Pragma("unroll")                                                        \
            for (int nt = 0; nt < 4; nt++) {                                         \
                const __nv_bfloat16* bp = Bw + (nt * 8 + gq) * LDH + k0;             \
                bfr[nt][0] = *(const uint32_t*)(bp + 2 * tg);                        \
                bfr[nt][1] = *(const uint32_t*)(bp + 2 * tg + 8);                    \
            }                                                                        \
            _Pragma("unroll")                                                        \
            for (int mt = 0; mt < 4; mt++) {                                         \
                uint32_t a0, a1, a2, a3;                                             \
                uint32_t addr = smem_cast(Aw + (mt * 16 + lm_row) * LDH + k0 + lm_kh); \
                asm volatile(                                                        \
                    "ldmatrix.sync.aligned.m8n8.x4.shared.b16 {%0,%1,%2,%3}, [%4];"  \
                    : "=r"(a0), "=r"(a1), "=r"(a2), "=r"(a3) : "r"(addr));           \
                _Pragma("unroll")                                                    \
                for (int nt = 0; nt < 4; nt++) {                                     \
                    asm volatile(                                                    \
                        "mma.sync.aligned.m16n8k16.row.col.f32.bf16.bf16.f32 "       \
                        "{%0,%1,%2,%3}, {%4,%5,%6,%7}, {%8,%9}, {%0,%1,%2,%3};"      \
                        : "+f"(acc[mt][nt][0]), "+f"(acc[mt][nt][1]),                \
                          "+f"(acc[mt][nt][2]), "+f"(acc[mt][nt][3])                 \
                        : "r"(a0), "r"(a1), "r"(a2), "r"(a3),                        \
                          "r"(bfr[nt][0]), "r"(bfr[nt][1]));                         \
                }                                                                    \
            }                                                                        \
        }                                                                            \
    }

// ---- merged QKV GEMM: N = 2304 (sectors: q | k | v), all-bf16 outputs ----
__global__ __launch_bounds__(256, 2)
void gemm_qkv(const __nv_bfloat16* __restrict__ A, const __nv_bfloat16* __restrict__ Wall,
              const float* __restrict__ bq, const float* __restrict__ bk,
              const float* __restrict__ bv,
              __nv_bfloat16* __restrict__ qh, __nv_bfloat16* __restrict__ kh,
              __nv_bfloat16* __restrict__ vh)
{
    extern __shared__ __nv_bfloat16 smh[];
    const int tid  = threadIdx.x;
    const int wid  = tid >> 5;
    const int lane = tid & 31;
    const int gq   = lane >> 2;
    const int tg   = lane & 3;
    const int wm   = wid >> 2;
    const int wn   = wid & 3;
    const int bm   = blockIdx.y * 128;
    const int bn   = blockIdx.x * 128;        // 0..2303
    const int sector = blockIdx.x / 6;        // 0=q 1=k 2=v
    const int cbase  = bn - sector * DD;

    const __nv_bfloat16* Ab = A + (size_t)bm * DD;
    const __nv_bfloat16* Wb = Wall + (size_t)bn * DD;

    GEMM_MAINLOOP(Ab, Wb)

    const float* bias = (sector == 0) ? bq : (sector == 1) ? bk : bv;
    const float alpha = (sector == 0) ? 0.125f : 1.0f;
    __nv_bfloat16* outp = (sector == 0) ? qh : (sector == 1) ? kh : vh;

#pragma unroll
    for (int mt = 0; mt < 4; mt++) {
        int r0 = bm + wm * 64 + mt * 16 + gq;
        int r1 = r0 + 8;
#pragma unroll
        for (int nt = 0; nt < 4; nt++) {
            int cl = cbase + wn * 32 + nt * 8 + tg * 2;
            float b0 = bias[cl], b1 = bias[cl + 1];
            *(__nv_bfloat162*)(outp + (size_t)r0 * DD + cl) =
                __floats2bfloat162_rn((acc[mt][nt][0] + b0) * alpha,
                                      (acc[mt][nt][1] + b1) * alpha);
            *(__nv_bfloat162*)(outp + (size_t)r1 * DD + cl) =
                __floats2bfloat162_rn((acc[mt][nt][2] + b0) * alpha,
                                      (acc[mt][nt][3] + b1) * alpha);
        }
    }
}

// ---- Wo GEMM: C = A @ Wo^T + bias + resid (fp32 out) ----
__global__ __launch_bounds__(256, 2)
void gemm_out(const __nv_bfloat16* __restrict__ A, const __nv_bfloat16* __restrict__ W,
              const float* __restrict__ bias, const float* __restrict__ resid,
              float* __restrict__ C)
{
    extern __shared__ __nv_bfloat16 smh[];
    const int tid  = threadIdx.x;
    const int wid  = tid >> 5;
    const int lane = tid & 31;
    const int gq   = lane >> 2;
    const int tg   = lane & 3;
    const int wm   = wid >> 2;
    const int wn   = wid & 3;
    const int bm   = blockIdx.y * 128;
    const int bn   = blockIdx.x * 128;

    const __nv_bfloat16* Ab = A + (size_t)bm * DD;
    const __nv_bfloat16* Wb = W + (size_t)bn * DD;

    GEMM_MAINLOOP(Ab, Wb)

#pragma unroll
    for (int mt = 0; mt < 4; mt++) {
        int r0 = bm + wm * 64 + mt * 16 + gq;
        int r1 = r0 + 8;
#pragma unroll
        for (int nt = 0; nt < 4; nt++) {
            int col = bn + wn * 32 + nt * 8 + tg * 2;
            float b0 = bias[col], b1 = bias[col + 1];
            float2 o0, o1;
            o0.x = acc[mt][nt][0] + b0 + resid[(size_t)r0 * DD + col];
            o0.y = acc[mt][nt][1] + b1 + resid[(size_t)r0 * DD + col + 1];
            o1.x = acc[mt][nt][2] + b0 + resid[(size_t)r1 * DD + col];
            o1.y = acc[mt][nt][3] + b1 + resid[(size_t)r1 * DD + col + 1];
            *(float2*)(C + (size_t)r0 * DD + col) = o0;
            *(float2*)(C + (size_t)r1 * DD + col) = o1;
        }
    }
}

// ---------------- CSR build ----------------
__global__ void hist_kernel(const int* __restrict__ dst)
{
    int e = blockIdx.x * blockDim.x + threadIdx.x;
    if (e < EE) atomicAdd(&g_cnt[dst[e]], 1);
}

// two-level warp-shuffle scan over 8192 counts (1024 threads x 8)
__global__ void scan_kernel()
{
    __shared__ int wsum[32];
    int t = threadIdx.x;
    int lane = t & 31, wid = t >> 5;
    int base = t * 8;
    int loc[8];
    int s = 0;
#pragma unroll
    for (int j = 0; j < 8; j++) { loc[j] = s; s += g_cnt[base + j]; }
    // inclusive warp scan of s
    int v = s;
#pragma unroll
    for (int off = 1; off < 32; off <<= 1) {
        int n = __shfl_up_sync(0xffffffffu, v, off);
        if (lane >= off) v += n;
    }
    if (lane == 31) wsum[wid] = v;
    __syncthreads();
    if (wid == 0) {
        int w = wsum[lane];
#pragma unroll
        for (int off = 1; off < 32; off <<= 1) {
            int n = __shfl_up_sync(0xffffffffu, w, off);
            if (lane >= off) w += n;
        }
        wsum[lane] = w;   // inclusive warp totals
    }
    __syncthreads();
    int warp_excl = (wid > 0) ? wsum[wid - 1] : 0;
    int excl = warp_excl + v - s;    // exclusive prefix for this thread's 8 slots
#pragma unroll
    for (int j = 0; j < 8; j++) {
        g_rowptr[base + j] = excl + loc[j];
        g_cursor[base + j] = excl + loc[j];
    }
    if (t == 1023) g_rowptr[NN] = wsum[31];
}

__global__ void scatter_kernel(const int* __restrict__ dst)
{
    int e = blockIdx.x * blockDim.x + threadIdx.x;
    if (e < EE) {
        int p = atomicAdd(&g_cursor[dst[e]], 1);
        g_csr_eid[p] = e;
    }
}

// per-row sort by edge id (deterministic order); 8 warps/block, warp per node
__global__ __launch_bounds__(256)
void sort_rows_kernel(const int* __restrict__ edge_src)
{
    __shared__ int sh[8][256];
    int w = threadIdx.x >> 5;
    int lane = threadIdx.x & 31;
    int n = blockIdx.x * 8 + w;
    int r0 = g_rowptr[n], r1 = g_rowptr[n + 1];
    int deg = r1 - r0;
    if (deg <= 256) {
        for (int i = lane; i < deg; i += 32) sh[w][i] = g_csr_eid[r0 + i];
        __syncwarp();
        for (int p = 0; p < deg; p++) {
            for (int i = (p & 1) + 2 * lane; i + 1 < deg; i += 64) {
                int a = sh[w][i], b = sh[w][i + 1];
                if (a > b) { sh[w][i] = b; sh[w][i + 1] = a; }
            }
            __syncwarp();
        }
        for (int i = lane; i < deg; i += 32) {
            int e = sh[w][i];
            g_csr_eid[r0 + i] = e;
            g_csr_src[r0 + i] = edge_src[e];
        }
    } else {  // pathological fallback (never hit): no sort, fill src only
        for (int i = lane; i < deg; i += 32) {
            int e = g_csr_eid[r0 + i];
            g_csr_src[r0 + i] = edge_src[e];
        }
    }
}

// ====== fused edge-score + softmax: warp per dst node, q in registers ======
#define SCAP 128
__global__ __launch_bounds__(256)
void score_softmax_kernel(const float* __restrict__ mask)
{
    __shared__ float sbuf[8][SCAP * HH];   // 48 KB
    int w = threadIdx.x >> 5;
    int lane = threadIdx.x & 31;
    int node = blockIdx.x * 8 + w;
    int r0 = g_rowptr[node], r1 = g_rowptr[node + 1];
    int deg = r1 - r0;
    bool m = (mask[node] >= 0.f);

    const __nv_bfloat162* qq = (const __nv_bfloat162*)(g_qh + (size_t)node * DD);
    float2 q2[HH];
#pragma unroll
    for (int h = 0; h < HH; h++) q2[h] = __bfloat1622float2(qq[h * 32 + lane]);

    if (deg <= SCAP) {
        for (int j = 0; j < deg; j++) {
            int src = g_csr_src[r0 + j];
            const __nv_bfloat162* kk = (const __nv_bfloat162*)(g_kh + (size_t)src * DD);
#pragma unroll
            for (int h = 0; h < HH; h++) {
                float2 a = __bfloat1622float2(kk[h * 32 + lane]);
                float p = a.x * q2[h].x + a.y * q2[h].y;
#pragma unroll
                for (int off = 16; off > 0; off >>= 1)
                    p += __shfl_xor_sync(0xffffffffu, p, off);
                if (lane == 0) sbuf[w][j * HH + h] = m ? p : -1e4f;
            }
        }
        __syncwarp();
        if (lane < HH) {
            float mx = -3.4e38f;
            for (int j = 0; j < deg; j++) mx = fmaxf(mx, sbuf[w][j * HH + lane]);
            float s = 0.f;
            for (int j = 0; j < deg; j++) {
                float e = expf(sbuf[w][j * HH + lane] - mx);
                sbuf[w][j * HH + lane] = e;
                s += e;
            }
            float inv = 1.f / s;
            for (int j = 0; j < deg; j++)
                g_score[(size_t)(r0 + j) * HH + lane] = sbuf[w][j * HH + lane] * inv;
        }
    } else {
        // fallback (never hit for this input)
        for (int j = 0; j < deg; j++) {
            int src = g_csr_src[r0 + j];
            const __nv_bfloat162* kk = (const __nv_bfloat162*)(g_kh + (size_t)src * DD);
#pragma unroll
            for (int h = 0; h < HH; h++) {
                float2 a = __bfloat1622float2(kk[h * 32 + lane]);
                float p = a.x * q2[h].x + a.y * q2[h].y;
#pragma unroll
                for (int off = 16; off > 0; off >>= 1)
                    p += __shfl_xor_sync(0xffffffffu, p, off);
                if (lane == 0) g_score[(size_t)(r0 + j) * HH + h] = m ? p : -1e4f;
            }
        }
        __syncwarp();
        if (lane < HH) {
            float mx = -3.4e38f;
            for (int j = 0; j < deg; j++)
                mx = fmaxf(mx, g_score[(size_t)(r0 + j) * HH + lane]);
            float s = 0.f;
            for (int j = 0; j < deg; j++)
                s += expf(g_score[(size_t)(r0 + j) * HH + lane] - mx);
            float inv = 1.f / s;
            for (int j = 0; j < deg; j++) {
                float e = expf(g_score[(size_t)(r0 + j) * HH + lane] - mx);
                g_score[(size_t)(r0 + j) * HH + lane] = e * inv;
            }
        }
    }
}

// -------- message passing: h_out = 0.9 * sum_e attn*h_in[src] + 0.1*v (bf16) ---
__global__ void mp_kernel(const __nv_bfloat16* __restrict__ hin,
                          __nv_bfloat16* __restrict__ hout)
{
    int n = blockIdx.x;
    int t = threadIdx.x;   // 128 threads; bf162 slots t, t+128, t+256
    int r0 = g_rowptr[n], r1 = g_rowptr[n + 1];
    int h0 = t >> 5;
    float2 a0 = {0.f, 0.f}, a1 = {0.f, 0.f}, a2 = {0.f, 0.f};
    for (int i = r0; i < r1; i++) {
        const __nv_bfloat162* hs =
            (const __nv_bfloat162*)(hin + (size_t)g_csr_src[i] * DD);
        const float* at = g_score + (size_t)i * HH;
        float w0 = at[h0], w1 = at[h0 + 4], w2 = at[h0 + 8];
        float2 x0 = __bfloat1622float2(hs[t]);
        float2 x1 = __bfloat1622float2(hs[t + 128]);
        float2 x2 = __bfloat1622float2(hs[t + 256]);
        a0.x = fmaf(w0, x0.x, a0.x); a0.y = fmaf(w0, x0.y, a0.y);
        a1.x = fmaf(w1, x1.x, a1.x); a1.y = fmaf(w1, x1.y, a1.y);
        a2.x = fmaf(w2, x2.x, a2.x); a2.y = fmaf(w2, x2.y, a2.y);
    }
    const __nv_bfloat162* vv = (const __nv_bfloat162*)(g_vh + (size_t)n * DD);
    float2 v0 = __bfloat1622float2(vv[t]);
    float2 v1 = __bfloat1622float2(vv[t + 128]);
    float2 v2 = __bfloat1622float2(vv[t + 256]);
    __nv_bfloat162* ob = (__nv_bfloat162*)(hout + (size_t)n * DD);
    ob[t]       = __floats2bfloat162_rn(0.9f * a0.x + 0.1f * v0.x,
                                        0.9f * a0.y + 0.1f * v0.y);
    ob[t + 128] = __floats2bfloat162_rn(0.9f * a1.x + 0.1f * v1.x,
                                        0.9f * a1.y + 0.1f * v1.y);
    ob[t + 256] = __floats2bfloat162_rn(0.9f * a2.x + 0.1f * v2.x,
                                        0.9f * a2.y + 0.1f * v2.y);
}

// ---------------- residual layernorm ----------------
__global__ void layernorm_kernel(const float* __restrict__ y,
                                 const float* __restrict__ gam,
                                 const float* __restrict__ bet,
                                 float* __restrict__ out)
{
    int row = blockIdx.x;
    int t = threadIdx.x;  // 256
    const float* yr = y + (size_t)row * DD;
    float v0 = yr[t], v1 = yr[t + 256], v2 = yr[t + 512];
    __shared__ float sh[256];
    sh[t] = v0 + v1 + v2;
    __syncthreads();
    for (int o = 128; o > 0; o >>= 1) { if (t < o) sh[t] += sh[t + o]; __syncthreads(); }
    float mu = sh[0] * (1.f / 768.f);
    __syncthreads();
    float d0 = v0 - mu, d1 = v1 - mu, d2 = v2 - mu;
    sh[t] = d0 * d0 + d1 * d1 + d2 * d2;
    __syncthreads();
    for (int o = 128; o > 0; o >>= 1) { if (t < o) sh[t] += sh[t + o]; __syncthreads(); }
    float inv = rsqrtf(sh[0] * (1.f / 768.f) + 1e-12f);
    float* orow = out + (size_t)row * DD;
    orow[t]       = d0 * inv * gam[t]       + bet[t];
    orow[t + 256] = d1 * inv * gam[t + 256] + bet[t + 256];
    orow[t + 512] = d2 * inv * gam[t + 512] + bet[t + 512];
}

// ---------------- launch ----------------
extern "C" void kernel_launch(void* const* d_in, const int* in_sizes, int n_in,
                              void* d_out, int out_size)
{
    const float* x    = (const float*)d_in[0];
    const float* mask = (const float*)d_in[1];
    const int*   esrc = (const int*)d_in[2];
    const int*   edst = (const int*)d_in[3];
    const float* Wq = (const float*)d_in[4];  const float* bq = (const float*)d_in[5];
    const float* Wk = (const float*)d_in[6];  const float* bk = (const float*)d_in[7];
    const float* Wv = (const float*)d_in[8];  const float* bv = (const float*)d_in[9];
    const float* Wo = (const float*)d_in[10]; const float* bo = (const float*)d_in[11];
    const float* lg = (const float*)d_in[12]; const float* lb = (const float*)d_in[13];
    float* out = (float*)d_out;

    float *yp;
    __nv_bfloat16 *xhp, *whp, *qhp, *khp, *vhp, *hb0p, *hb1p;
    int* cntp;
    cudaGetSymbolAddress((void**)&yp,   g_y);
    cudaGetSymbolAddress((void**)&xhp,  g_xh);
    cudaGetSymbolAddress((void**)&whp,  g_wh);
    cudaGetSymbolAddress((void**)&qhp,  g_qh);
    cudaGetSymbolAddress((void**)&khp,  g_kh);
    cudaGetSymbolAddress((void**)&vhp,  g_vh);
    cudaGetSymbolAddress((void**)&hb0p, g_hb0);
    cudaGetSymbolAddress((void**)&hb1p, g_hb1);
    cudaGetSymbolAddress((void**)&cntp, g_cnt);

    __nv_bfloat16* woh = whp + 3 * (size_t)DD * DD;

    cudaFuncSetAttribute(gemm_qkv, cudaFuncAttributeMaxDynamicSharedMemorySize, GEMM_SMEM);
    cudaFuncSetAttribute(gemm_out, cudaFuncAttributeMaxDynamicSharedMemorySize, GEMM_SMEM);

    // ---- fused fp32 -> bf16 conversion (x + 4 weights, one launch) ----
    {
        int total = NN * DD / 4 + 4 * (DD * DD / 4);
        cvt_all_kernel<<<(total + 255) / 256, 256>>>(
            (const float4*)x, (const float4*)Wq, (const float4*)Wk,
            (const float4*)Wv, (const float4*)Wo,
            (__nv_bfloat162*)xhp, (__nv_bfloat162*)whp);
    }

    // ---- merged q/k/v projection: one GEMM, N = 2304 ----
    {
        dim3 qkvgrid(3 * DD / 128, NN / 128);   // (18, 64)
        gemm_qkv<<<qkvgrid, 256, GEMM_SMEM>>>(xhp, whp, bq, bk, bv, qhp, khp, vhp);
    }

    // CSR build (deterministic: per-row sort by edge id)
    cudaMemsetAsync(cntp, 0, NN * sizeof(int), 0);
    hist_kernel<<<(EE + 255) / 256, 256>>>(edst);
    scan_kernel<<<1, 1024>>>();
    scatter_kernel<<<(EE + 255) / 256, 256>>>(edst);
    sort_rows_kernel<<<NN / 8, 256>>>(esrc);

    // fused edge scores + per-dst softmax (warp per node)
    score_softmax_kernel<<<NN / 8, 256>>>(mask);

    // 5 message-passing steps (bf16 ping-pong)
    mp_kernel<<<NN, 128>>>(vhp,  hb0p);
    mp_kernel<<<NN, 128>>>(hb0p, hb1p);
    mp_kernel<<<NN, 128>>>(hb1p, hb0p);
    mp_kernel<<<NN, 128>>>(hb0p, hb1p);
    mp_kernel<<<NN, 128>>>(hb1p, hb0p);

    // output projection + residual, then layernorm
    {
        dim3 ogrid(DD / 128, NN / 128);         // (6, 64)
        gemm_out<<<ogrid, 256, GEMM_SMEM>>>(hb0p, woh, bo, x, yp);
    }
    layernorm_kernel<<<NN, 256>>>(yp, lg, lb, out);
}

// round 12
// speedup vs baseline: 3.6035x; 1.0466x over previous
#include <cuda_runtime.h>
#include <cuda_bf16.h>
#include <cstdint>
#include <math.h>

// Problem constants
#define NN   8192          // B*S nodes
#define DD   768           // hidden dim
#define EE   131072        // edges
#define HH   12            // heads
#define HDD  64            // head dim

// ---------------- scratch (static device globals; no allocation) ----------------
__device__ float g_y[NN * DD];
__device__ __nv_bfloat16 g_xh[NN * DD];    // hidden_states bf16 (GEMM A input)
__device__ __nv_bfloat16 g_wh[4 * DD * DD];// Wq,Wk,Wv,Wo bf16 (contiguous)
__device__ __nv_bfloat16 g_qh[NN * DD];    // q (bf16, pre-scaled)
__device__ __nv_bfloat16 g_kh[NN * DD];    // k (bf16)
__device__ __nv_bfloat16 g_vh[NN * DD];    // v (bf16: gather + mix term)
__device__ __nv_bfloat16 g_hb0[NN * DD];   // h ping (bf16)
__device__ __nv_bfloat16 g_hb1[NN * DD];   // h pong (bf16)
__device__ float g_score[EE * HH];         // attn weights
__device__ int   g_cnt[NN];
__device__ int   g_rowptr[NN + 1];
__device__ int   g_cursor[NN];
__device__ int   g_csr_eid[EE];
__device__ int   g_csr_src[EE];

// ---- side stream + fork/join events (host static init; no device memory) ----
namespace {
struct AuxStreams {
    cudaStream_t side = nullptr;
    cudaEvent_t fork = nullptr, join = nullptr;
    AuxStreams() {
        cudaStreamCreateWithFlags(&side, cudaStreamNonBlocking);
        cudaEventCreateWithFlags(&fork, cudaEventDisableTiming);
        cudaEventCreateWithFlags(&join, cudaEventDisableTiming);
    }
};
AuxStreams g_aux;
}

__device__ __forceinline__ uint32_t smem_cast(const void* p) {
    return (uint32_t)__cvta_generic_to_shared(p);
}

// ------------- fused fp32 -> bf16 conversion (x + all 4 weights, one launch) ----
__global__ void cvt_all_kernel(const float4* __restrict__ x,
                               const float4* __restrict__ wq, const float4* __restrict__ wk,
                               const float4* __restrict__ wv, const float4* __restrict__ wo,
                               __nv_bfloat162* __restrict__ xh, __nv_bfloat162* __restrict__ wh)
{
    const int NX = NN * DD / 4;
    const int NW = DD * DD / 4;
    int i = blockIdx.x * blockDim.x + threadIdx.x;
    if (i >= NX + 4 * NW) return;
    float4 v;
    __nv_bfloat162* d;
    if (i < NX) {
        v = x[i];
        d = xh + 2 * (size_t)i;
    } else {
        int j = i - NX;
        int w = j / NW, o = j - w * NW;
        const float4* s = (w == 0) ? wq : (w == 1) ? wk : (w == 2) ? wv : wo;
        v = s[o];
        d = wh + 2 * (size_t)j;
    }
    d[0] = __floats2bfloat162_rn(v.x, v.y);
    d[1] = __floats2bfloat162_rn(v.z, v.w);
}

// ================= bf16 warp-MMA GEMM (m16n8k16, ldmatrix A, 3-stage) =====
#define BKK    32                        // k-step (bf16 elems)
#define LDH    40                        // 32 + 8 pad bf16 per row
#define STG_H  (128 * LDH * 2)           // bf16 elems per stage (A + B)
#define GST    3
#define GEMM_SMEM (GST * STG_H * 2)      // bytes = 61440
#define NKT    (DD / BKK)                // 24

#define GEMM_MAINLOOP(Ab, Wb)                                                        \
    float acc[4][4][4];                                                              \
    _Pragma("unroll")                                                                \
    for (int mt = 0; mt < 4; mt++)                                                   \
        _Pragma("unroll")                                                            \
        for (int nt = 0; nt < 4; nt++)                                               \
            _Pragma("unroll")                                                        \
            for (int c = 0; c < 4; c++) acc[mt][nt][c] = 0.f;                        \
    auto load_stage = [&](int kt, int stg) {                                         \
        __nv_bfloat16* Abase = smh + stg * STG_H;                                    \
        __nv_bfloat16* Bbase = Abase + 128 * LDH;                                    \
        _Pragma("unroll")                                                            \
        for (int i = 0; i < 2; i++) {                                                \
            int idx = tid + i * 256;                                                 \
            int row = idx >> 2;                                                      \
            int c16 = idx & 3;                                                       \
            const __nv_bfloat16* ga = Ab + (size_t)row * DD + kt * BKK + c16 * 8;    \
            const __nv_bfloat16* gb = Wb + (size_t)row * DD + kt * BKK + c16 * 8;    \
            uint32_t da = smem_cast(Abase + row * LDH + c16 * 8);                    \
            uint32_t db = smem_cast(Bbase + row * LDH + c16 * 8);                    \
            asm volatile("cp.async.cg.shared.global [%0], [%1], 16;" :: "r"(da), "l"(ga)); \
            asm volatile("cp.async.cg.shared.global [%0], [%1], 16;" :: "r"(db), "l"(gb)); \
        }                                                                            \
        asm volatile("cp.async.commit_group;");                                      \
    };                                                                               \
    load_stage(0, 0);                                                                \
    load_stage(1, 1);                                                                \
    const int lm_row = lane & 15;                                                    \
    const int lm_kh  = (lane >> 4) * 8;                                              \
    for (int kt = 0; kt < NKT; kt++) {                                               \
        if (kt + 1 < NKT) { asm volatile("cp.async.wait_group 1;"); }                \
        else              { asm volatile("cp.async.wait_group 0;"); }                \
        __syncthreads();                                                             \
        if (kt + 2 < NKT) load_stage(kt + 2, (kt + 2) % GST);                        \
        const __nv_bfloat16* Abase = smh + (kt % GST) * STG_H;                       \
        const __nv_bfloat16* Bbase = Abase + 128 * LDH;                              \
        const __nv_bfloat16* Aw = Abase + (wm * 64) * LDH;                           \
        const __nv_bfloat16* Bw = Bbase + (wn * 32) * LDH;                           \
        _Pragma("unroll")                                                            \
        for (int ks = 0; ks < 2; ks++) {                                             \
            const int k0 = ks * 16;                                                  \
            uint32_t bfr[4][2];                                                      \
            _Pragma("unroll")                                                        \
            for (int nt = 0; nt < 4; nt++) {                                         \
                const __nv_bfloat16* bp = Bw + (nt * 8 + gq) * LDH + k0;             \
                bfr[nt][0] = *(const uint32_t*)(bp + 2 * tg);                        \
                bfr[nt][1] = *(const uint32_t*)(bp + 2 * tg + 8);                    \
            }                                                                        \
            _Pragma("unroll")                                                        \
            for (int mt = 0; mt < 4; mt++) {                                         \
                uint32_t a0, a1, a2, a3;                                             \
                uint32_t addr = smem_cast(Aw + (mt * 16 + lm_row) * LDH + k0 + lm_kh); \
                asm volatile(                                                        \
                    "ldmatrix.sync.aligned.m8n8.x4.shared.b16 {%0,%1,%2,%3}, [%4];"  \
                    : "=r"(a0), "=r"(a1), "=r"(a2), "=r"(a3) : "r"(addr));           \
                _Pragma("unroll")                                                    \
                for (int nt = 0; nt < 4; nt++) {                                     \
                    asm volatile(                                                    \
                        "mma.sync.aligned.m16n8k16.row.col.f32.bf16.bf16.f32 "       \
                        "{%0,%1,%2,%3}, {%4,%5,%6,%7}, {%8,%9}, {%0,%1,%2,%3};"      \
                        : "+f"(acc[mt][nt][0]), "+f"(acc[mt][nt][1]),                \
                          "+f"(acc[mt][nt][2]), "+f"(acc[mt][nt][3])                 \
                        : "r"(a0), "r"(a1), "r"(a2), "r"(a3),                        \
                          "r"(bfr[nt][0]), "r"(bfr[nt][1]));                         \
                }                                                                    \
            }                                                                        \
        }                                                                            \
    }

// ---- merged QKV GEMM: N = 2304 (sectors: q | k | v), all-bf16 outputs ----
__global__ __launch_bounds__(256, 2)
void gemm_qkv(const __nv_bfloat16* __restrict__ A, const __nv_bfloat16* __restrict__ Wall,
              const float* __restrict__ bq, const float* __restrict__ bk,
              const float* __restrict__ bv,
              __nv_bfloat16* __restrict__ qh, __nv_bfloat16* __restrict__ kh,
              __nv_bfloat16* __restrict__ vh)
{
    extern __shared__ __nv_bfloat16 smh[];
    const int tid  = threadIdx.x;
    const int wid  = tid >> 5;
    const int lane = tid & 31;
    const int gq   = lane >> 2;
    const int tg   = lane & 3;
    const int wm   = wid >> 2;
    const int wn   = wid & 3;
    const int bm   = blockIdx.y * 128;
    const int bn   = blockIdx.x * 128;        // 0..2303
    const int sector = blockIdx.x / 6;        // 0=q 1=k 2=v
    const int cbase  = bn - sector * DD;

    const __nv_bfloat16* Ab = A + (size_t)bm * DD;
    const __nv_bfloat16* Wb = Wall + (size_t)bn * DD;

    GEMM_MAINLOOP(Ab, Wb)

    const float* bias = (sector == 0) ? bq : (sector == 1) ? bk : bv;
    const float alpha = (sector == 0) ? 0.125f : 1.0f;
    __nv_bfloat16* outp = (sector == 0) ? qh : (sector == 1) ? kh : vh;

#pragma unroll
    for (int mt = 0; mt < 4; mt++) {
        int r0 = bm + wm * 64 + mt * 16 + gq;
        int r1 = r0 + 8;
#pragma unroll
        for (int nt = 0; nt < 4; nt++) {
            int cl = cbase + wn * 32 + nt * 8 + tg * 2;
            float b0 = bias[cl], b1 = bias[cl + 1];
            *(__nv_bfloat162*)(outp + (size_t)r0 * DD + cl) =
                __floats2bfloat162_rn((acc[mt][nt][0] + b0) * alpha,
                                      (acc[mt][nt][1] + b1) * alpha);
            *(__nv_bfloat162*)(outp + (size_t)r1 * DD + cl) =
                __floats2bfloat162_rn((acc[mt][nt][2] + b0) * alpha,
                                      (acc[mt][nt][3] + b1) * alpha);
        }
    }
}

// ---- Wo GEMM: C = A @ Wo^T + bias + resid (fp32 out) ----
__global__ __launch_bounds__(256, 2)
void gemm_out(const __nv_bfloat16* __restrict__ A, const __nv_bfloat16* __restrict__ W,
              const float* __restrict__ bias, const float* __restrict__ resid,
              float* __restrict__ C)
{
    extern __shared__ __nv_bfloat16 smh[];
    const int tid  = threadIdx.x;
    const int wid  = tid >> 5;
    const int lane = tid & 31;
    const int gq   = lane >> 2;
    const int tg   = lane & 3;
    const int wm   = wid >> 2;
    const int wn   = wid & 3;
    const int bm   = blockIdx.y * 128;
    const int bn   = blockIdx.x * 128;

    const __nv_bfloat16* Ab = A + (size_t)bm * DD;
    const __nv_bfloat16* Wb = W + (size_t)bn * DD;

    GEMM_MAINLOOP(Ab, Wb)

#pragma unroll
    for (int mt = 0; mt < 4; mt++) {
        int r0 = bm + wm * 64 + mt * 16 + gq;
        int r1 = r0 + 8;
#pragma unroll
        for (int nt = 0; nt < 4; nt++) {
            int col = bn + wn * 32 + nt * 8 + tg * 2;
            float b0 = bias[col], b1 = bias[col + 1];
            float2 o0, o1;
            o0.x = acc[mt][nt][0] + b0 + resid[(size_t)r0 * DD + col];
            o0.y = acc[mt][nt][1] + b1 + resid[(size_t)r0 * DD + col + 1];
            o1.x = acc[mt][nt][2] + b0 + resid[(size_t)r1 * DD + col];
            o1.y = acc[mt][nt][3] + b1 + resid[(size_t)r1 * DD + col + 1];
            *(float2*)(C + (size_t)r0 * DD + col) = o0;
            *(float2*)(C + (size_t)r1 * DD + col) = o1;
        }
    }
}

// ---------------- CSR build ----------------
__global__ void hist_kernel(const int* __restrict__ dst)
{
    int e = blockIdx.x * blockDim.x + threadIdx.x;
    if (e < EE) atomicAdd(&g_cnt[dst[e]], 1);
}

// two-level warp-shuffle scan over 8192 counts (1024 threads x 8)
__global__ void scan_kernel()
{
    __shared__ int wsum[32];
    int t = threadIdx.x;
    int lane = t & 31, wid = t >> 5;
    int base = t * 8;
    int loc[8];
    int s = 0;
#pragma unroll
    for (int j = 0; j < 8; j++) { loc[j] = s; s += g_cnt[base + j]; }
    int v = s;
#pragma unroll
    for (int off = 1; off < 32; off <<= 1) {
        int n = __shfl_up_sync(0xffffffffu, v, off);
        if (lane >= off) v += n;
    }
    if (lane == 31) wsum[wid] = v;
    __syncthreads();
    if (wid == 0) {
        int w = wsum[lane];
#pragma unroll
        for (int off = 1; off < 32; off <<= 1) {
            int n = __shfl_up_sync(0xffffffffu, w, off);
            if (lane >= off) w += n;
        }
        wsum[lane] = w;
    }
    __syncthreads();
    int warp_excl = (wid > 0) ? wsum[wid - 1] : 0;
    int excl = warp_excl + v - s;
#pragma unroll
    for (int j = 0; j < 8; j++) {
        g_rowptr[base + j] = excl + loc[j];
        g_cursor[base + j] = excl + loc[j];
    }
    if (t == 1023) g_rowptr[NN] = wsum[31];
}

__global__ void scatter_kernel(const int* __restrict__ dst)
{
    int e = blockIdx.x * blockDim.x + threadIdx.x;
    if (e < EE) {
        int p = atomicAdd(&g_cursor[dst[e]], 1);
        g_csr_eid[p] = e;
    }
}

// per-row sort by edge id (deterministic order); 8 warps/block, warp per node
__global__ __launch_bounds__(256)
void sort_rows_kernel(const int* __restrict__ edge_src)
{
    __shared__ int sh[8][256];
    int w = threadIdx.x >> 5;
    int lane = threadIdx.x & 31;
    int n = blockIdx.x * 8 + w;
    int r0 = g_rowptr[n], r1 = g_rowptr[n + 1];
    int deg = r1 - r0;
    if (deg <= 256) {
        for (int i = lane; i < deg; i += 32) sh[w][i] = g_csr_eid[r0 + i];
        __syncwarp();
        for (int p = 0; p < deg; p++) {
            for (int i = (p & 1) + 2 * lane; i + 1 < deg; i += 64) {
                int a = sh[w][i], b = sh[w][i + 1];
                if (a > b) { sh[w][i] = b; sh[w][i + 1] = a; }
            }
            __syncwarp();
        }
        for (int i = lane; i < deg; i += 32) {
            int e = sh[w][i];
            g_csr_eid[r0 + i] = e;
            g_csr_src[r0 + i] = edge_src[e];
        }
    } else {
        for (int i = lane; i < deg; i += 32) {
            int e = g_csr_eid[r0 + i];
            g_csr_src[r0 + i] = edge_src[e];
        }
    }
}

// ====== fused edge-score + softmax: warp per dst node, q in registers ======
#define SCAP 128
__global__ __launch_bounds__(256)
void score_softmax_kernel(const float* __restrict__ mask)
{
    __shared__ float sbuf[8][SCAP * HH];   // 48 KB
    int w = threadIdx.x >> 5;
    int lane = threadIdx.x & 31;
    int node = blockIdx.x * 8 + w;
    int r0 = g_rowptr[node], r1 = g_rowptr[node + 1];
    int deg = r1 - r0;
    bool m = (mask[node] >= 0.f);

    const __nv_bfloat162* qq = (const __nv_bfloat162*)(g_qh + (size_t)node * DD);
    float2 q2[HH];
#pragma unroll
    for (int h = 0; h < HH; h++) q2[h] = __bfloat1622float2(qq[h * 32 + lane]);

    if (deg <= SCAP) {
        for (int j = 0; j < deg; j++) {
            int src = g_csr_src[r0 + j];
            const __nv_bfloat162* kk = (const __nv_bfloat162*)(g_kh + (size_t)src * DD);
#pragma unroll
            for (int h = 0; h < HH; h++) {
                float2 a = __bfloat1622float2(kk[h * 32 + lane]);
                float p = a.x * q2[h].x + a.y * q2[h].y;
#pragma unroll
                for (int off = 16; off > 0; off >>= 1)
                    p += __shfl_xor_sync(0xffffffffu, p, off);
                if (lane == 0) sbuf[w][j * HH + h] = m ? p : -1e4f;
            }
        }
        __syncwarp();
        if (lane < HH) {
            float mx = -3.4e38f;
            for (int j = 0; j < deg; j++) mx = fmaxf(mx, sbuf[w][j * HH + lane]);
            float s = 0.f;
            for (int j = 0; j < deg; j++) {
                float e = expf(sbuf[w][j * HH + lane] - mx);
                sbuf[w][j * HH + lane] = e;
                s += e;
            }
            float inv = 1.f / s;
            for (int j = 0; j < deg; j++)
                g_score[(size_t)(r0 + j) * HH + lane] = sbuf[w][j * HH + lane] * inv;
        }
    } else {
        for (int j = 0; j < deg; j++) {
            int src = g_csr_src[r0 + j];
            const __nv_bfloat162* kk = (const __nv_bfloat162*)(g_kh + (size_t)src * DD);
#pragma unroll
            for (int h = 0; h < HH; h++) {
                float2 a = __bfloat1622float2(kk[h * 32 + lane]);
                float p = a.x * q2[h].x + a.y * q2[h].y;
#pragma unroll
                for (int off = 16; off > 0; off >>= 1)
                    p += __shfl_xor_sync(0xffffffffu, p, off);
                if (lane == 0) g_score[(size_t)(r0 + j) * HH + h] = m ? p : -1e4f;
            }
        }
        __syncwarp();
        if (lane < HH) {
            float mx = -3.4e38f;
            for (int j = 0; j < deg; j++)
                mx = fmaxf(mx, g_score[(size_t)(r0 + j) * HH + lane]);
            float s = 0.f;
            for (int j = 0; j < deg; j++)
                s += expf(g_score[(size_t)(r0 + j) * HH + lane] - mx);
            float inv = 1.f / s;
            for (int j = 0; j < deg; j++) {
                float e = expf(g_score[(size_t)(r0 + j) * HH + lane] - mx);
                g_score[(size_t)(r0 + j) * HH + lane] = e * inv;
            }
        }
    }
}

// -------- message passing: h_out = 0.9 * sum_e attn*h_in[src] + 0.1*v (bf16) ---
__global__ void mp_kernel(const __nv_bfloat16* __restrict__ hin,
                          __nv_bfloat16* __restrict__ hout)
{
    int n = blockIdx.x;
    int t = threadIdx.x;   // 128 threads; bf162 slots t, t+128, t+256
    int r0 = g_rowptr[n], r1 = g_rowptr[n + 1];
    int h0 = t >> 5;
    float2 a0 = {0.f, 0.f}, a1 = {0.f, 0.f}, a2 = {0.f, 0.f};
    for (int i = r0; i < r1; i++) {
        const __nv_bfloat162* hs =
            (const __nv_bfloat162*)(hin + (size_t)g_csr_src[i] * DD);
        const float* at = g_score + (size_t)i * HH;
        float w0 = at[h0], w1 = at[h0 + 4], w2 = at[h0 + 8];
        float2 x0 = __bfloat1622float2(hs[t]);
        float2 x1 = __bfloat1622float2(hs[t + 128]);
        float2 x2 = __bfloat1622float2(hs[t + 256]);
        a0.x = fmaf(w0, x0.x, a0.x); a0.y = fmaf(w0, x0.y, a0.y);
        a1.x = fmaf(w1, x1.x, a1.x); a1.y = fmaf(w1, x1.y, a1.y);
        a2.x = fmaf(w2, x2.x, a2.x); a2.y = fmaf(w2, x2.y, a2.y);
    }
    const __nv_bfloat162* vv = (const __nv_bfloat162*)(g_vh + (size_t)n * DD);
    float2 v0 = __bfloat1622float2(vv[t]);
    float2 v1 = __bfloat1622float2(vv[t + 128]);
    float2 v2 = __bfloat1622float2(vv[t + 256]);
    __nv_bfloat162* ob = (__nv_bfloat162*)(hout + (size_t)n * DD);
    ob[t]       = __floats2bfloat162_rn(0.9f * a0.x + 0.1f * v0.x,
                                        0.9f * a0.y + 0.1f * v0.y);
    ob[t + 128] = __floats2bfloat162_rn(0.9f * a1.x + 0.1f * v1.x,
                                        0.9f * a1.y + 0.1f * v1.y);
    ob[t + 256] = __floats2bfloat162_rn(0.9f * a2.x + 0.1f * v2.x,
                                        0.9f * a2.y + 0.1f * v2.y);
}

// ---------------- residual layernorm ----------------
__global__ void layernorm_kernel(const float* __restrict__ y,
                                 const float* __restrict__ gam,
                                 const float* __restrict__ bet,
                                 float* __restrict__ out)
{
    int row = blockIdx.x;
    int t = threadIdx.x;  // 256
    const float* yr = y + (size_t)row * DD;
    float v0 = yr[t], v1 = yr[t + 256], v2 = yr[t + 512];
    __shared__ float sh[256];
    sh[t] = v0 + v1 + v2;
    __syncthreads();
    for (int o = 128; o > 0; o >>= 1) { if (t < o) sh[t] += sh[t + o]; __syncthreads(); }
    float mu = sh[0] * (1.f / 768.f);
    __syncthreads();
    float d0 = v0 - mu, d1 = v1 - mu, d2 = v2 - mu;
    sh[t] = d0 * d0 + d1 * d1 + d2 * d2;
    __syncthreads();
    for (int o = 128; o > 0; o >>= 1) { if (t < o) sh[t] += sh[t + o]; __syncthreads(); }
    float inv = rsqrtf(sh[0] * (1.f / 768.f) + 1e-12f);
    float* orow = out + (size_t)row * DD;
    orow[t]       = d0 * inv * gam[t]       + bet[t];
    orow[t + 256] = d1 * inv * gam[t + 256] + bet[t + 256];
    orow[t + 512] = d2 * inv * gam[t + 512] + bet[t + 512];
}

// ---------------- launch ----------------
extern "C" void kernel_launch(void* const* d_in, const int* in_sizes, int n_in,
                              void* d_out, int out_size)
{
    const float* x    = (const float*)d_in[0];
    const float* mask = (const float*)d_in[1];
    const int*   esrc = (const int*)d_in[2];
    const int*   edst = (const int*)d_in[3];
    const float* Wq = (const float*)d_in[4];  const float* bq = (const float*)d_in[5];
    const float* Wk = (const float*)d_in[6];  const float* bk = (const float*)d_in[7];
    const float* Wv = (const float*)d_in[8];  const float* bv = (const float*)d_in[9];
    const float* Wo = (const float*)d_in[10]; const float* bo = (const float*)d_in[11];
    const float* lg = (const float*)d_in[12]; const float* lb = (const float*)d_in[13];
    float* out = (float*)d_out;

    float *yp;
    __nv_bfloat16 *xhp, *whp, *qhp, *khp, *vhp, *hb0p, *hb1p;
    int* cntp;
    cudaGetSymbolAddress((void**)&yp,   g_y);
    cudaGetSymbolAddress((void**)&xhp,  g_xh);
    cudaGetSymbolAddress((void**)&whp,  g_wh);
    cudaGetSymbolAddress((void**)&qhp,  g_qh);
    cudaGetSymbolAddress((void**)&khp,  g_kh);
    cudaGetSymbolAddress((void**)&vhp,  g_vh);
    cudaGetSymbolAddress((void**)&hb0p, g_hb0);
    cudaGetSymbolAddress((void**)&hb1p, g_hb1);
    cudaGetSymbolAddress((void**)&cntp, g_cnt);

    __nv_bfloat16* woh = whp + 3 * (size_t)DD * DD;

    cudaFuncSetAttribute(gemm_qkv, cudaFuncAttributeMaxDynamicSharedMemorySize, GEMM_SMEM);
    cudaFuncSetAttribute(gemm_out, cudaFuncAttributeMaxDynamicSharedMemorySize, GEMM_SMEM);

    // ---- FORK: CSR build on side stream, concurrent with cvt + qkv GEMM ----
    cudaEventRecord(g_aux.fork, 0);
    cudaStreamWaitEvent(g_aux.side, g_aux.fork, 0);

    // side stream: CSR build (depends only on edge_src/edge_dst)
    cudaMemsetAsync(cntp, 0, NN * sizeof(int), g_aux.side);
    hist_kernel<<<(EE + 255) / 256, 256, 0, g_aux.side>>>(edst);
    scan_kernel<<<1, 1024, 0, g_aux.side>>>();
    scatter_kernel<<<(EE + 255) / 256, 256, 0, g_aux.side>>>(edst);
    sort_rows_kernel<<<NN / 8, 256, 0, g_aux.side>>>(esrc);
    cudaEventRecord(g_aux.join, g_aux.side);

    // main stream: conversions + merged q/k/v projection
    {
        int total = NN * DD / 4 + 4 * (DD * DD / 4);
        cvt_all_kernel<<<(total + 255) / 256, 256>>>(
            (const float4*)x, (const float4*)Wq, (const float4*)Wk,
            (const float4*)Wv, (const float4*)Wo,
            (__nv_bfloat162*)xhp, (__nv_bfloat162*)whp);
    }
    {
        dim3 qkvgrid(3 * DD / 128, NN / 128);   // (18, 64)
        gemm_qkv<<<qkvgrid, 256, GEMM_SMEM>>>(xhp, whp, bq, bk, bv, qhp, khp, vhp);
    }

    // ---- JOIN: score needs both q/k (main) and CSR (side) ----
    cudaStreamWaitEvent(0, g_aux.join, 0);

    // fused edge scores + per-dst softmax (warp per node)
    score_softmax_kernel<<<NN / 8, 256>>>(mask);

    // 5 message-passing steps (bf16 ping-pong)
    mp_kernel<<<NN, 128>>>(vhp,  hb0p);
    mp_kernel<<<NN, 128>>>(hb0p, hb1p);
    mp_kernel<<<NN, 128>>>(hb1p, hb0p);
    mp_kernel<<<NN, 128>>>(hb0p, hb1p);
    mp_kernel<<<NN, 128>>>(hb1p, hb0p);

    // output projection + residual, then layernorm
    {
        dim3 ogrid(DD / 128, NN / 128);         // (6, 64)
        gemm_out<<<ogrid, 256, GEMM_SMEM>>>(hb0p, woh, bo, x, yp);
    }
    layernorm_kernel<<<NN, 256>>>(yp, lg, lb, out);
}